// round 2
// baseline (speedup 1.0000x reference)
#include <cuda_runtime.h>

// Problem constants (B=1, C=2, H=W=64, k1=k2=36, k3=2, iters=6 -> 5 steps)
#define HW    4096
#define MDIM  8192          // m = C*H*W
#define MK    64            // mk = H*W/64
#define KK1   36
#define KK2   36
#define KK3   2
#define KC    2592          // k1*k2*k3
#define NSTEPS 5

// -------- persistent device state (no allocation allowed) --------
__device__ float g_L  [MDIM];
__device__ float g_S  [MDIM];
__device__ float g_Mt [MK * MDIM];   // M^T : [r][p]   (2 MB)
__device__ float g_N  [MK * KC];     // N   : [r][col]
__device__ float g_Gt [MK * MDIM];   // (AkL @ N^T)^T : [r][p]
__device__ float g_T  [MK * KC];     // M^T @ AkL     : [r][col]
__device__ float g_Cm [MK * MK];
__device__ float g_Inv[MK * MK];
__device__ float g_Acc[MDIM];        // Ak_adj accumulator (x Kc)

// ---------------- init: L=img, S=S0, Mt=eye, N=eye ----------------
__global__ void k_init(const float* __restrict__ img, const float* __restrict__ S0) {
    int idx = blockIdx.x * 256 + threadIdx.x;     // grid covers MK*MDIM
    if (idx < MDIM) { g_L[idx] = img[idx]; g_S[idx] = S0[idx]; }
    if (idx < MK * MDIM) {
        int r = idx >> 13, p = idx & (MDIM - 1);
        g_Mt[idx] = (p == r) ? 1.0f : 0.0f;
    }
    if (idx < MK * KC) {
        int r = idx / KC, c = idx - r * KC;
        g_N[idx] = (c == r) ? 1.0f : 0.0f;
    }
}

// ---------------- zero accumulators (Acc, T) ----------------
__global__ void k_zero() {
    int idx = blockIdx.x * 256 + threadIdx.x;     // grid covers MK*KC
    if (idx < MDIM)    g_Acc[idx] = 0.0f;
    if (idx < MK * KC) g_T[idx]   = 0.0f;
}

// ---------------- op A: Acc[p] += sum_col Mt_old[r, p+(k,i,j)] * N[r,col] ----------------
// block = (hc in 0..7, r in 0..63); each block: full Mt row r + full N row r in smem.
// thread: w = tid&63, g=tid>>6 -> (c, h-group of 4). Sliding register window over h (i loop).
__global__ void __launch_bounds__(256) k_opA() {
    __shared__ float Ms[MDIM];          // Mt row r, [c][h][w] pitch 64
    __shared__ float Fs[KC];            // N row r
    int r  = blockIdx.y;
    int hc = blockIdx.x;
    int tid = threadIdx.x;
    for (int i = tid; i < MDIM; i += 256) Ms[i] = g_Mt[r * MDIM + i];
    for (int i = tid; i < KC;   i += 256) Fs[i] = g_N[r * KC + i];
    __syncthreads();

    int w = tid & 63;
    int g = tid >> 6;
    int c = g & 1;
    int hbase = hc * 8 + (g >> 1) * 4;   // this thread covers h = hbase..hbase+3

    float a0 = 0.f, a1 = 0.f, a2 = 0.f, a3 = 0.f;
    for (int k = 0; k < KK3; k++) {
        int cp = ((c + k) & 1) << 12;
        for (int j = 0; j < KK2; j++) {
            int wcol = (w + j) & 63;
            float m0 = Ms[cp + ((hbase    ) & 63) * 64 + wcol];
            float m1 = Ms[cp + ((hbase + 1) & 63) * 64 + wcol];
            float m2 = Ms[cp + ((hbase + 2) & 63) * 64 + wcol];
            int fb = (k * KK2 + j) * KK1;
            #pragma unroll 4
            for (int i = 0; i < KK1; i++) {
                float m3 = Ms[cp + ((hbase + i + 3) & 63) * 64 + wcol];
                float f  = Fs[fb + i];
                a0 += m0 * f; a1 += m1 * f; a2 += m2 * f; a3 += m3 * f;
                m0 = m1; m1 = m2; m2 = m3;
            }
        }
    }
    int pb = c * HW + hbase * 64 + w;
    atomicAdd(&g_Acc[pb      ], a0);
    atomicAdd(&g_Acc[pb +  64], a1);
    atomicAdd(&g_Acc[pb + 128], a2);
    atomicAdd(&g_Acc[pb + 192], a3);
}

// ---------------- elementwise L/S update ----------------
__global__ void k_elem(const float* __restrict__ img,
                       const float* __restrict__ pg, const float* __restrict__ pb) {
    int p = blockIdx.x * 256 + threadIdx.x;
    if (p >= MDIM) return;
    float gam = *pg, bet = *pb;
    float akadj = g_Acc[p] * (1.0f / (float)KC);
    float ln = (img[p] - g_S[p] + gam * akadj) / (gam + 1.0f);
    ln = fminf(fmaxf(ln, 0.0f), 1.0f);
    g_L[p] = ln;
    g_S[p] = (img[p] - ln) / (bet + 1.0f);
}

// ---------------- gram: g_Cm = alpha*I + 2*gamma * X X^T  (X row-major [64][K]) ----------------
// which: 0 -> X=g_N (K=2592), 1 -> X=g_Mt (K=8192)
__global__ void __launch_bounds__(256) k_gram(int which,
                                              const float* __restrict__ pa,
                                              const float* __restrict__ pg) {
    __shared__ float Xa[MDIM];
    const float* X = which ? g_Mt : g_N;
    int K = which ? MDIM : KC;
    int a = blockIdx.x;
    int tid = threadIdx.x;
    for (int i = tid; i < K; i += 256) Xa[i] = X[a * K + i];
    __syncthreads();
    int warp = tid >> 5, lane = tid & 31;
    for (int b = warp; b < MK; b += 8) {
        const float* xb = X + b * K;
        float s = 0.f;
        for (int kk = lane; kk < K; kk += 32) s += Xa[kk] * xb[kk];
        #pragma unroll
        for (int o = 16; o; o >>= 1) s += __shfl_xor_sync(0xffffffffu, s, o);
        if (lane == 0) {
            float v = 2.0f * (*pg) * s;
            if (a == b) v += *pa;
            g_Cm[a * MK + b] = v;
        }
    }
}

// ---------------- 64x64 SPD inverse (Gauss-Jordan, no pivoting): g_Inv = inv(g_Cm) ----------------
__global__ void __launch_bounds__(256) k_inv() {
    __shared__ float aug[64][129];
    __shared__ float colk[64];
    int tid = threadIdx.x;
    for (int idx = tid; idx < 64 * 128; idx += 256) {
        int i = idx >> 7, j = idx & 127;
        aug[i][j] = (j < 64) ? g_Cm[i * 64 + j] : ((j - 64 == i) ? 1.0f : 0.0f);
    }
    __syncthreads();
    for (int k = 0; k < 64; k++) {
        float pinv = 1.0f / aug[k][k];      // all threads read (post-sync)
        __syncthreads();
        if (tid < 128)                 aug[k][tid] *= pinv;           // scale row k
        else if (tid < 192)            colk[tid - 128] = aug[tid - 128][k]; // save col k
        __syncthreads();
        for (int idx = tid; idx < 64 * 128; idx += 256) {
            int i = idx >> 7, j = idx & 127;
            if (i != k) aug[i][j] -= colk[i] * aug[k][j];
        }
        __syncthreads();
    }
    for (int idx = tid; idx < 64 * 64; idx += 256) {
        int i = idx >> 6, j = idx & 63;
        g_Inv[idx] = aug[i][64 + j];
    }
}

// ---------------- op B: Gt[r, p=(c,h,w)] = sum_{k,j,i} N[r,(k,j,i)] * L[(c-k),(h-i),(w-j)] ----------
// block = (h in 0..63, c in 0..1); full L in smem (pitch 65), N streamed per (k,j).
// 4r x 4w register tile per thread.
__global__ void __launch_bounds__(256) k_opB() {
    __shared__ float Ls[2 * 64 * 65];   // [c][row][w] pitch 65
    __shared__ float Ns[64 * 36];       // N[:, (k,j,*)] slab
    int h = blockIdx.x, c = blockIdx.y;
    int tid = threadIdx.x;
    for (int i = tid; i < MDIM; i += 256) {
        int cc = i >> 12, rw = i & 4095;
        Ls[cc * 4160 + (rw >> 6) * 65 + (rw & 63)] = g_L[i];
    }
    int w4 = tid & 15;       // w = w4*4 + t
    int r4 = tid >> 4;       // r = r4*4 + u
    float acc[4][4];
    #pragma unroll
    for (int u = 0; u < 4; u++)
        #pragma unroll
        for (int t = 0; t < 4; t++) acc[u][t] = 0.f;

    for (int k = 0; k < KK3; k++) {
        int lplane = ((c - k) & 1) * 4160;
        for (int j = 0; j < KK2; j++) {
            __syncthreads();
            for (int idx = tid; idx < 64 * 36; idx += 256) {
                int rr = idx / 36, ii = idx - rr * 36;
                Ns[idx] = g_N[rr * KC + (k * KK2 + j) * KK1 + ii];
            }
            __syncthreads();
            #pragma unroll 4
            for (int i = 0; i < KK1; i++) {
                int lrow = lplane + ((h - i) & 63) * 65;
                float f0 = Ns[(r4 * 4 + 0) * 36 + i];
                float f1 = Ns[(r4 * 4 + 1) * 36 + i];
                float f2 = Ns[(r4 * 4 + 2) * 36 + i];
                float f3 = Ns[(r4 * 4 + 3) * 36 + i];
                float l0 = Ls[lrow + ((w4 * 4 + 0 - j) & 63)];
                float l1 = Ls[lrow + ((w4 * 4 + 1 - j) & 63)];
                float l2 = Ls[lrow + ((w4 * 4 + 2 - j) & 63)];
                float l3 = Ls[lrow + ((w4 * 4 + 3 - j) & 63)];
                acc[0][0] += f0 * l0; acc[0][1] += f0 * l1; acc[0][2] += f0 * l2; acc[0][3] += f0 * l3;
                acc[1][0] += f1 * l0; acc[1][1] += f1 * l1; acc[1][2] += f1 * l2; acc[1][3] += f1 * l3;
                acc[2][0] += f2 * l0; acc[2][1] += f2 * l1; acc[2][2] += f2 * l2; acc[2][3] += f2 * l3;
                acc[3][0] += f3 * l0; acc[3][1] += f3 * l1; acc[3][2] += f3 * l2; acc[3][3] += f3 * l3;
            }
        }
    }
    int pbase = c * HW + h * 64 + w4 * 4;
    #pragma unroll
    for (int u = 0; u < 4; u++)
        #pragma unroll
        for (int t = 0; t < 4; t++)
            g_Gt[(r4 * 4 + u) * MDIM + pbase + t] = acc[u][t];
}

// ---------------- op C: T[r, col=(k,j,i)] += sum_p Mt[r,p] * L[(c-k),(h-i),(w-j)] ------------------
// block = (j 0..35, k 0..1, hhalf 0..1); full L in smem, Mt streamed in 64x32 slabs.
// 4r x 3i register tile, 192 threads. atomicAdd over the two h-halves.
__global__ void __launch_bounds__(192) k_opC() {
    __shared__ float Ls[2 * 64 * 65];    // [c][row][w] pitch 65
    __shared__ float Mts[64 * 33];       // [r][wl] pitch 33
    int j  = blockIdx.x;
    int k  = blockIdx.y;
    int hh = blockIdx.z;
    int tid = threadIdx.x;
    for (int i = tid; i < MDIM; i += 192) {
        int cc = i >> 12, rw = i & 4095;
        Ls[cc * 4160 + (rw >> 6) * 65 + (rw & 63)] = g_L[i];
    }
    int r_grp = tid / 12;          // 0..15 -> r = r_grp*4 + u
    int i_grp = tid - r_grp * 12;  // 0..11 -> i = i_grp*3 + v
    float acc[4][3];
    #pragma unroll
    for (int u = 0; u < 4; u++)
        #pragma unroll
        for (int v = 0; v < 3; v++) acc[u][v] = 0.f;

    for (int s = 0; s < 128; s++) {            // c(1b) | hloc(5b) | wh(1b)
        int wh   = s & 1;
        int hloc = (s >> 1) & 31;
        int c    = s >> 6;
        int h    = hh * 32 + hloc;
        __syncthreads();
        for (int idx = tid; idx < 64 * 32; idx += 192) {
            int rr = idx >> 5, wl = idx & 31;
            Mts[rr * 33 + wl] = g_Mt[rr * MDIM + c * HW + h * 64 + wh * 32 + wl];
        }
        __syncthreads();
        int cm = ((c - k) & 1) * 4160;
        int ro0 = cm + ((h - (i_grp * 3 + 0)) & 63) * 65;
        int ro1 = cm + ((h - (i_grp * 3 + 1)) & 63) * 65;
        int ro2 = cm + ((h - (i_grp * 3 + 2)) & 63) * 65;
        int wb = wh * 32;
        #pragma unroll 4
        for (int wl = 0; wl < 32; wl++) {
            int wj = (wb + wl - j) & 63;
            float l0 = Ls[ro0 + wj];
            float l1 = Ls[ro1 + wj];
            float l2 = Ls[ro2 + wj];
            float m0 = Mts[(r_grp * 4 + 0) * 33 + wl];
            float m1 = Mts[(r_grp * 4 + 1) * 33 + wl];
            float m2 = Mts[(r_grp * 4 + 2) * 33 + wl];
            float m3 = Mts[(r_grp * 4 + 3) * 33 + wl];
            acc[0][0] += m0 * l0; acc[0][1] += m0 * l1; acc[0][2] += m0 * l2;
            acc[1][0] += m1 * l0; acc[1][1] += m1 * l1; acc[1][2] += m1 * l2;
            acc[2][0] += m2 * l0; acc[2][1] += m2 * l1; acc[2][2] += m2 * l2;
            acc[3][0] += m3 * l0; acc[3][1] += m3 * l1; acc[3][2] += m3 * l2;
        }
    }
    int colb = (k * KK2 + j) * KK1 + i_grp * 3;
    #pragma unroll
    for (int u = 0; u < 4; u++)
        #pragma unroll
        for (int v = 0; v < 3; v++)
            atomicAdd(&g_T[(r_grp * 4 + u) * KC + colb + v], acc[u][v]);
}

// ---------------- small mm: out = 2*gamma * g_Inv @ X   ([64][Kcols]) --------------------------
// which: 0 -> out=g_Mt, X=g_Gt, K=8192;  1 -> out=g_N, X=g_T, K=2592
__global__ void __launch_bounds__(256) k_smallmm(int which, const float* __restrict__ pg) {
    __shared__ float As[64 * 64];
    __shared__ float Xs[64 * 64];
    float* out      = which ? g_N : g_Mt;
    const float* X  = which ? g_T : g_Gt;
    int Kcols       = which ? KC  : MDIM;
    int tx = threadIdx.x;         // 0..63 (column within block)
    int ty = threadIdx.y;         // 0..3  (r-quarter: 16 rows each)
    int tid = ty * 64 + tx;
    int cb = blockIdx.x * 64;
    for (int i = tid; i < 4096; i += 256) As[i] = g_Inv[i];
    for (int i = tid; i < 4096; i += 256) {
        int q = i >> 6, cc = cb + (i & 63);
        Xs[i] = (cc < Kcols) ? X[q * Kcols + cc] : 0.0f;
    }
    __syncthreads();
    float acc[16];
    #pragma unroll
    for (int u = 0; u < 16; u++) acc[u] = 0.f;
    for (int q = 0; q < 64; q++) {
        float xv = Xs[q * 64 + tx];
        #pragma unroll
        for (int u = 0; u < 16; u++)
            acc[u] += As[(ty * 16 + u) * 64 + q] * xv;
    }
    int col = cb + tx;
    if (col < Kcols) {
        float sc = 2.0f * (*pg);
        #pragma unroll
        for (int u = 0; u < 16; u++)
            out[(ty * 16 + u) * Kcols + col] = sc * acc[u];
    }
}

// ---------------- final copy ----------------
__global__ void k_copy(float* __restrict__ out) {
    int p = blockIdx.x * 256 + threadIdx.x;
    if (p < MDIM) out[p] = g_L[p];
}

// =====================================================================================
extern "C" void kernel_launch(void* const* d_in, const int* in_sizes, int n_in,
                              void* d_out, int out_size) {
    const float* img = (const float*)d_in[0];
    const float* S0  = (const float*)d_in[1];
    const float* pa  = (const float*)d_in[2];   // alpha
    const float* pb  = (const float*)d_in[3];   // beta
    const float* pg  = (const float*)d_in[4];   // gamma
    float* out = (float*)d_out;
    (void)in_sizes; (void)n_in; (void)out_size;

    k_init<<<(MK * MDIM + 255) / 256, 256>>>(img, S0);

    for (int it = 0; it < NSTEPS; it++) {
        k_zero<<<(MK * KC + 255) / 256, 256>>>();
        k_opA<<<dim3(8, 64), 256>>>();                       // Ak_adj(M@N) -> Acc (old Mt, old N)
        k_elem<<<(MDIM + 255) / 256, 256>>>(img, pg, pb);    // L, S update
        k_gram<<<64, 256>>>(0, pa, pg);                      // Cm = aI + 2g N N^T
        k_inv<<<1, 256>>>();                                 // Inv = inv(Cm)
        k_opB<<<dim3(64, 2), 256>>>();                       // Gt = (AkL @ N^T)^T  (new L, old N)
        k_smallmm<<<MDIM / 64, dim3(64, 4)>>>(0, pg);        // Mt = 2g Inv @ Gt
        k_gram<<<64, 256>>>(1, pa, pg);                      // Cn = aI + 2g Mt Mt^T
        k_inv<<<1, 256>>>();                                 // Inv = inv(Cn)
        k_opC<<<dim3(36, 2, 2), 192>>>();                    // T = Mt @ AkL
        k_smallmm<<<(KC + 63) / 64, dim3(64, 4)>>>(1, pg);   // N = 2g Inv @ T
    }
    k_copy<<<(MDIM + 255) / 256, 256>>>(out);
}

// round 5
// speedup vs baseline: 1.9839x; 1.9839x over previous
#include <cuda_runtime.h>

// Problem constants (B=1, C=2, H=W=64, k1=k2=36, k3=2, iters=6 -> 5 steps)
#define HW    4096
#define MDIM  8192          // m = C*H*W
#define MK    64            // mk = H*W/64
#define KK1   36
#define KK2   36
#define KK3   2
#define KC    2592          // k1*k2*k3
#define NSTEPS 5

// -------- persistent device state (no allocation allowed) --------
__device__ float g_L  [MDIM];
__device__ float g_S  [MDIM];
__device__ float g_Mt [MK * MDIM];   // M^T : [r][p]   (2 MB)
__device__ float g_N  [MK * KC];     // N   : [r][col]
__device__ float g_Gt [MK * MDIM];   // (AkL @ N^T)^T : [r][p]
__device__ float g_T  [MK * KC];     // M^T @ AkL     : [r][col]
__device__ float g_Cm [MK * MK];
__device__ float g_Inv[MK * MK];
__device__ float g_Acc[MDIM];        // Ak_adj accumulator (x Kc)

// ---------------- init: L=img, S=S0, Mt=eye, N=eye ----------------
__global__ void k_init(const float* __restrict__ img, const float* __restrict__ S0) {
    int idx = blockIdx.x * 256 + threadIdx.x;     // grid covers MK*MDIM
    if (idx < MDIM) { g_L[idx] = img[idx]; g_S[idx] = S0[idx]; }
    if (idx < MK * MDIM) {
        int r = idx >> 13, p = idx & (MDIM - 1);
        g_Mt[idx] = (p == r) ? 1.0f : 0.0f;
    }
    if (idx < MK * KC) {
        int r = idx / KC, c = idx - r * KC;
        g_N[idx] = (c == r) ? 1.0f : 0.0f;
    }
}

// ---------------- zero accumulators (Acc, T, Gt) ----------------
__global__ void k_zero() {
    int idx = blockIdx.x * 256 + threadIdx.x;     // grid covers MK*MDIM
    if (idx < MK * MDIM) g_Gt[idx] = 0.0f;
    if (idx < MK * KC)   g_T[idx]  = 0.0f;
    if (idx < MDIM)      g_Acc[idx] = 0.0f;
}

// ---------------- op A: Acc[p] += sum_r sum_col Mt[r, adj(p,col)] * N[r,col] ----------------
// grid (4 hc, 64 r), 256 threads. h-expanded Mt row in smem (rows 0..98, no wrap math).
// thread: w = tid&63, g = tid>>6 -> (c = g&1, ho = (g>>1)*8). 8 h-outputs via sliding window.
__global__ void __launch_bounds__(256) k_opA() {
    __shared__ float Msx[2 * 6336];     // [cc][hx<99][w] pitch 64  (50.7 KB)
    __shared__ float Fs[KC];            // N row r (10.4 KB)
    int hc = blockIdx.x;
    int r  = blockIdx.y;
    int tid = threadIdx.x;
    const float* Mrow = g_Mt + r * MDIM;
    for (int idx = tid; idx < 2 * 6336; idx += 256) {
        int cc = idx / 6336; int rem = idx - cc * 6336;
        int hx = rem >> 6;   int w = rem & 63;
        int hh = (hx >= 64) ? hx - 64 : hx;
        Msx[idx] = Mrow[cc * 4096 + hh * 64 + w];
    }
    for (int idx = tid; idx < KC; idx += 256) Fs[idx] = g_N[r * KC + idx];
    __syncthreads();

    int w = tid & 63;
    int g = tid >> 6;
    int c = g & 1;
    int hb = hc * 16 + (g >> 1) * 8;

    float a0=0.f,a1=0.f,a2=0.f,a3=0.f,a4=0.f,a5=0.f,a6=0.f,a7=0.f;
    for (int k = 0; k < KK3; k++) {
        int cp = ((c + k) & 1) * 6336;
        const float* fpk = Fs + k * (KK2 * KK1);
        for (int j = 0; j < KK2; j++) {
            int wcol = w + j; if (wcol >= 64) wcol -= 64;
            const float* mp = Msx + cp + hb * 64 + wcol;
            const float* fp = fpk + j * KK1;
            float w0 = mp[0*64], w1 = mp[1*64], w2 = mp[2*64], w3 = mp[3*64];
            float w4 = mp[4*64], w5 = mp[5*64], w6 = mp[6*64];
            #pragma unroll
            for (int i = 0; i < KK1; i++) {
                float w7 = mp[(i + 7) * 64];
                float f  = fp[i];
                a0 += w0 * f; a1 += w1 * f; a2 += w2 * f; a3 += w3 * f;
                a4 += w4 * f; a5 += w5 * f; a6 += w6 * f; a7 += w7 * f;
                w0 = w1; w1 = w2; w2 = w3; w3 = w4; w4 = w5; w5 = w6; w6 = w7;
            }
        }
    }
    int pb = c * 4096 + hb * 64 + w;
    atomicAdd(&g_Acc[pb + 0*64], a0);
    atomicAdd(&g_Acc[pb + 1*64], a1);
    atomicAdd(&g_Acc[pb + 2*64], a2);
    atomicAdd(&g_Acc[pb + 3*64], a3);
    atomicAdd(&g_Acc[pb + 4*64], a4);
    atomicAdd(&g_Acc[pb + 5*64], a5);
    atomicAdd(&g_Acc[pb + 6*64], a6);
    atomicAdd(&g_Acc[pb + 7*64], a7);
}

// ---------------- elementwise L/S update ----------------
__global__ void k_elem(const float* __restrict__ img,
                       const float* __restrict__ pg, const float* __restrict__ pb) {
    int p = blockIdx.x * 256 + threadIdx.x;
    if (p >= MDIM) return;
    float gam = *pg, bet = *pb;
    float akadj = g_Acc[p] * (1.0f / (float)KC);
    float ln = (img[p] - g_S[p] + gam * akadj) / (gam + 1.0f);
    ln = fminf(fmaxf(ln, 0.0f), 1.0f);
    g_L[p] = ln;
    g_S[p] = (img[p] - ln) / (bet + 1.0f);
}

// ---------------- gram: g_Cm = alpha*I + 2*gamma * X X^T  (X row-major [64][K]) ----------------
__global__ void __launch_bounds__(256) k_gram(int which,
                                              const float* __restrict__ pa,
                                              const float* __restrict__ pg) {
    __shared__ float Xa[MDIM];
    const float* X = which ? g_Mt : g_N;
    int K = which ? MDIM : KC;
    int a = blockIdx.x;
    int tid = threadIdx.x;
    for (int i = tid; i < K; i += 256) Xa[i] = X[a * K + i];
    __syncthreads();
    int warp = tid >> 5, lane = tid & 31;
    for (int b = warp; b < MK; b += 8) {
        const float* xb = X + b * K;
        float s = 0.f;
        for (int kk = lane; kk < K; kk += 32) s += Xa[kk] * xb[kk];
        #pragma unroll
        for (int o = 16; o; o >>= 1) s += __shfl_xor_sync(0xffffffffu, s, o);
        if (lane == 0) {
            float v = 2.0f * (*pg) * s;
            if (a == b) v += *pa;
            g_Cm[a * MK + b] = v;
        }
    }
}

// ---------------- 64x64 SPD inverse (Gauss-Jordan, no pivoting) ----------------
__global__ void __launch_bounds__(256) k_inv() {
    __shared__ float aug[64][129];
    __shared__ float colk[64];
    int tid = threadIdx.x;
    for (int idx = tid; idx < 64 * 128; idx += 256) {
        int i = idx >> 7, j = idx & 127;
        aug[i][j] = (j < 64) ? g_Cm[i * 64 + j] : ((j - 64 == i) ? 1.0f : 0.0f);
    }
    __syncthreads();
    for (int k = 0; k < 64; k++) {
        float pinv = 1.0f / aug[k][k];
        __syncthreads();
        if (tid < 128)       aug[k][tid] *= pinv;
        else if (tid < 192)  colk[tid - 128] = aug[tid - 128][k];
        __syncthreads();
        for (int idx = tid; idx < 64 * 128; idx += 256) {
            int i = idx >> 7, j = idx & 127;
            if (i != k) aug[i][j] -= colk[i] * aug[k][j];
        }
        __syncthreads();
    }
    for (int idx = tid; idx < 64 * 64; idx += 256) {
        int i = idx >> 6, j = idx & 63;
        g_Inv[idx] = aug[i][64 + j];
    }
}

// ---------------- op B: Gt[r, p=(c,h,w)] += sum_{j,i} N[r,(k,j,i)] * L[(c-k),(h-i),(w-j)] -------
// grid (64 h, 2 c, 2 k) = 256 blocks; source L plane cs=(c+k)&1 fixed, w-haloed in smem.
// 4r x 4w (w-interleaved by 16) register tile; N slab double-buffered via register prefetch.
__global__ void __launch_bounds__(256) k_opB() {
    __shared__ float Lx[64 * 100];      // [hh][t]  t = (w-j)+36, value L[cs,hh,(t+28)&63]  (25.6 KB)
    __shared__ float Ns[2][2304];       // [r*36+i] per j, double buffered (18.4 KB)
    int h = blockIdx.x;
    int c = blockIdx.y;
    int k = blockIdx.z;
    int tid = threadIdx.x;
    int cs = (c + k) & 1;
    for (int idx = tid; idx < 6400; idx += 256) {
        int hh = idx / 100; int t = idx - hh * 100;
        Lx[idx] = g_L[cs * 4096 + hh * 64 + ((t + 28) & 63)];
    }
    const float* Nbase = g_N + k * (KK2 * KK1);
    float pre[9];
    #pragma unroll
    for (int q = 0; q < 9; q++) {
        int idx = tid + q * 256;
        int rr = idx / 36, ii = idx - rr * 36;
        pre[q] = Nbase[rr * KC + ii];          // j = 0
    }
    #pragma unroll
    for (int q = 0; q < 9; q++) Ns[0][tid + q * 256] = pre[q];
    __syncthreads();

    int wq = tid & 15;
    int rq = tid >> 4;
    int r0 = rq * 4;
    float acc[4][4];
    #pragma unroll
    for (int u = 0; u < 4; u++)
        #pragma unroll
        for (int t = 0; t < 4; t++) acc[u][t] = 0.f;

    for (int j = 0; j < KK2; j++) {
        if (j < KK2 - 1) {
            #pragma unroll
            for (int q = 0; q < 9; q++) {
                int idx = tid + q * 256;
                int rr = idx / 36, ii = idx - rr * 36;
                pre[q] = Nbase[rr * KC + (j + 1) * 36 + ii];
            }
        }
        const float* nb = Ns[j & 1];
        int wb = wq + 36 - j;
        #pragma unroll
        for (int i = 0; i < KK1; i++) {
            int hs = (h - i) & 63;
            const float* lp = Lx + hs * 100 + wb;
            float l0 = lp[0], l1 = lp[16], l2 = lp[32], l3 = lp[48];
            float f0 = nb[(r0 + 0) * 36 + i];
            float f1 = nb[(r0 + 1) * 36 + i];
            float f2 = nb[(r0 + 2) * 36 + i];
            float f3 = nb[(r0 + 3) * 36 + i];
            acc[0][0] += f0 * l0; acc[0][1] += f0 * l1; acc[0][2] += f0 * l2; acc[0][3] += f0 * l3;
            acc[1][0] += f1 * l0; acc[1][1] += f1 * l1; acc[1][2] += f1 * l2; acc[1][3] += f1 * l3;
            acc[2][0] += f2 * l0; acc[2][1] += f2 * l1; acc[2][2] += f2 * l2; acc[2][3] += f2 * l3;
            acc[3][0] += f3 * l0; acc[3][1] += f3 * l1; acc[3][2] += f3 * l2; acc[3][3] += f3 * l3;
        }
        __syncthreads();
        if (j < KK2 - 1) {
            #pragma unroll
            for (int q = 0; q < 9; q++) Ns[(j + 1) & 1][tid + q * 256] = pre[q];
            __syncthreads();
        }
    }
    int pb = c * 4096 + h * 64 + wq;
    #pragma unroll
    for (int u = 0; u < 4; u++)
        #pragma unroll
        for (int t = 0; t < 4; t++)
            atomicAdd(&g_Gt[(r0 + u) * MDIM + pb + 16 * t], acc[u][t]);
}

// ---------------- op C: T[r,col] += sum_{c,h,w} L[c,h,w] * Mt[r, adj((c,h,w),col)] ------------
// grid (64 r, 4 hq) = 256 blocks. Full Mt row w-haloed (pitch 101, plane pitch 6480 — bank-clean),
// L h-quarter in smem. Warp handles (k,i) pairs; lane = (c,hl) row; 36 j-outputs via sliding window.
__global__ void __launch_bounds__(256) k_opC() {
    __shared__ float Mtx[2 * 6480];     // [cs][hh][t<101], plane pitch 6480  (51.8 KB)
    __shared__ float Lsm[2 * 16 * 65];  // [c][hl][w] pitch 65 (8.3 KB)
    int r  = blockIdx.x;
    int hq = blockIdx.y;
    int tid = threadIdx.x;
    const float* Mrow = g_Mt + r * MDIM;
    for (int idx = tid; idx < 2 * 6464; idx += 256) {
        int cs = idx / 6464; int rem = idx - cs * 6464;
        int hh = rem / 101;  int t = rem - hh * 101;
        Mtx[cs * 6480 + hh * 101 + t] = Mrow[cs * 4096 + hh * 64 + ((t >= 64) ? t - 64 : t)];
    }
    for (int idx = tid; idx < 2048; idx += 256) {
        int cc = idx >> 10; int hl = (idx >> 6) & 15; int w = idx & 63;
        Lsm[(cc * 16 + hl) * 65 + w] = g_L[cc * 4096 + (hq * 16 + hl) * 64 + w];
    }
    __syncthreads();

    int warp = tid >> 5, lane = tid & 31;
    int c = lane >> 4, hl = lane & 15;
    int h = hq * 16 + hl;
    const float* lrow = Lsm + (c * 16 + hl) * 65;

    for (int kp = warp; kp < 72; kp += 8) {
        int k = (kp >= 36) ? 1 : 0;
        int i = kp - k * 36;
        int cs = (c + k) & 1;
        int hs = (h + i) & 63;
        const float* mrow = Mtx + cs * 6480 + hs * 101;

        float acc[36];
        #pragma unroll
        for (int t = 0; t < 36; t++) acc[t] = 0.f;
        float win[35];
        #pragma unroll
        for (int t = 0; t < 35; t++) win[t] = mrow[t];

        #pragma unroll
        for (int w = 0; w < 64; w++) {
            float lv = lrow[w];
            float nv = mrow[w + 35];
            #pragma unroll
            for (int t = 0; t < 35; t++) acc[t] += lv * win[t];
            acc[35] += lv * nv;
            #pragma unroll
            for (int t = 0; t < 34; t++) win[t] = win[t + 1];
            win[34] = nv;
        }

        int colb = r * KC + k * (KK2 * KK1) + i;   // + jj*36
        #pragma unroll
        for (int jj = 0; jj < 36; jj++) {
            float s = acc[jj];
            s += __shfl_xor_sync(0xffffffffu, s, 16);
            s += __shfl_xor_sync(0xffffffffu, s, 8);
            s += __shfl_xor_sync(0xffffffffu, s, 4);
            s += __shfl_xor_sync(0xffffffffu, s, 2);
            s += __shfl_xor_sync(0xffffffffu, s, 1);
            if (lane == (jj & 31)) atomicAdd(&g_T[colb + jj * 36], s);
        }
    }
}

// ---------------- small mm: out = 2*gamma * g_Inv @ X   ([64][Kcols]) --------------------------
__global__ void __launch_bounds__(256) k_smallmm(int which, const float* __restrict__ pg) {
    __shared__ float As[64 * 64];
    __shared__ float Xs[64 * 64];
    float* out      = which ? g_N : g_Mt;
    const float* X  = which ? g_T : g_Gt;
    int Kcols       = which ? KC  : MDIM;
    int tx = threadIdx.x;
    int ty = threadIdx.y;
    int tid = ty * 64 + tx;
    int cb = blockIdx.x * 64;
    for (int i = tid; i < 4096; i += 256) As[i] = g_Inv[i];
    for (int i = tid; i < 4096; i += 256) {
        int q = i >> 6, cc = cb + (i & 63);
        Xs[i] = (cc < Kcols) ? X[q * Kcols + cc] : 0.0f;
    }
    __syncthreads();
    float acc[16];
    #pragma unroll
    for (int u = 0; u < 16; u++) acc[u] = 0.f;
    for (int q = 0; q < 64; q++) {
        float xv = Xs[q * 64 + tx];
        #pragma unroll
        for (int u = 0; u < 16; u++)
            acc[u] += As[(ty * 16 + u) * 64 + q] * xv;
    }
    int col = cb + tx;
    if (col < Kcols) {
        float sc = 2.0f * (*pg);
        #pragma unroll
        for (int u = 0; u < 16; u++)
            out[(ty * 16 + u) * Kcols + col] = sc * acc[u];
    }
}

// ---------------- final copy ----------------
__global__ void k_copy(float* __restrict__ out) {
    int p = blockIdx.x * 256 + threadIdx.x;
    if (p < MDIM) out[p] = g_L[p];
}

// =====================================================================================
extern "C" void kernel_launch(void* const* d_in, const int* in_sizes, int n_in,
                              void* d_out, int out_size) {
    const float* img = (const float*)d_in[0];
    const float* S0  = (const float*)d_in[1];
    const float* pa  = (const float*)d_in[2];   // alpha
    const float* pb  = (const float*)d_in[3];   // beta
    const float* pg  = (const float*)d_in[4];   // gamma
    float* out = (float*)d_out;
    (void)in_sizes; (void)n_in; (void)out_size;

    k_init<<<(MK * MDIM + 255) / 256, 256>>>(img, S0);

    for (int it = 0; it < NSTEPS; it++) {
        k_zero<<<(MK * MDIM + 255) / 256, 256>>>();
        k_opA<<<dim3(4, 64), 256>>>();                       // Ak_adj(M@N) -> Acc
        k_elem<<<(MDIM + 255) / 256, 256>>>(img, pg, pb);    // L, S update
        if (it < NSTEPS - 1) {                               // final step only needs L
            k_gram<<<64, 256>>>(0, pa, pg);                  // Cm = aI + 2g N N^T
            k_inv<<<1, 256>>>();
            k_opB<<<dim3(64, 2, 2), 256>>>();                // Gt = (AkL @ N^T)^T
            k_smallmm<<<MDIM / 64, dim3(64, 4)>>>(0, pg);    // Mt = 2g Inv @ Gt
            k_gram<<<64, 256>>>(1, pa, pg);                  // Cn = aI + 2g Mt Mt^T
            k_inv<<<1, 256>>>();
            k_opC<<<dim3(64, 4), 256>>>();                   // T = Mt @ AkL
            k_smallmm<<<(KC + 63) / 64, dim3(64, 4)>>>(1, pg); // N = 2g Inv @ T
        }
    }
    k_copy<<<(MDIM + 255) / 256, 256>>>(out);
}

// round 7
// speedup vs baseline: 2.1915x; 1.1046x over previous
#include <cuda_runtime.h>

// Problem constants (B=1, C=2, H=W=64, k1=k2=36, k3=2, iters=6 -> 5 steps)
#define HW    4096
#define MDIM  8192
#define MK    64
#define KK1   36
#define KK2   36
#define KK3   2
#define KC    2592
#define NSTEPS 5

// -------- persistent device state --------
__device__ float g_L  [MDIM];
__device__ float g_S  [MDIM];
__device__ float g_Mt [MK * MDIM];     // M^T : [r][p]
__device__ float g_N  [MK * KC];       // N   : [r][col]
__device__ float g_GtP[8 * MK * MDIM]; // opB partials per (k,jg)  (16.8 MB)
__device__ float g_T  [MK * KC];       // M^T @ AkL
__device__ float g_Cm [MK * MK];
__device__ float g_Inv[MK * MK];
__device__ float g_Acc[MDIM];

__device__ __forceinline__ void cp_async4(void* sm, const void* gm) {
    unsigned sa = (unsigned)__cvta_generic_to_shared(sm);
    asm volatile("cp.async.ca.shared.global [%0], [%1], 4;" :: "r"(sa), "l"(gm));
}

// ---------------- init: L=img, S=S0, Mt=eye, N=eye, Acc=0 ----------------
__global__ void k_init(const float* __restrict__ img, const float* __restrict__ S0) {
    int idx = blockIdx.x * 256 + threadIdx.x;
    if (idx < MDIM) { g_L[idx] = img[idx]; g_S[idx] = S0[idx]; g_Acc[idx] = 0.0f; }
    if (idx < MK * MDIM) {
        int r = idx >> 13, p = idx & (MDIM - 1);
        g_Mt[idx] = (p == r) ? 1.0f : 0.0f;
    }
    if (idx < MK * KC) {
        int r = idx / KC, c = idx - r * KC;
        g_N[idx] = (c == r) ? 1.0f : 0.0f;
    }
}

// ---------------- role: gram  g_Cm = alpha*I + 2*gamma * X X^T ----------------
__device__ void gram_role(float* buf, int which, int a,
                          const float* pa, const float* pg, int NT, int tid) {
    const float* X = which ? g_Mt : g_N;
    int K = which ? MDIM : KC;
    for (int i = tid; i < K; i += NT) buf[i] = X[a * K + i];
    __syncthreads();
    int warp = tid >> 5, lane = tid & 31, nw = NT >> 5;
    for (int b = warp; b < MK; b += nw) {
        const float* xb = X + b * K;
        float s = 0.f;
        for (int kk = lane; kk < K; kk += 32) s += buf[kk] * xb[kk];
        #pragma unroll
        for (int o = 16; o; o >>= 1) s += __shfl_xor_sync(0xffffffffu, s, o);
        if (lane == 0) {
            float v = 2.0f * (*pg) * s;
            if (a == b) v += *pa;
            g_Cm[a * MK + b] = v;
        }
    }
}

// ---------------- role: 64x64 SPD inverse (Gauss-Jordan), generic NT ----------------
__device__ void inv_role(float* buf, int NT, int tid) {
    float* aug  = buf;            // 64*129 = 8256
    float* colk = buf + 8256;     // 64
    for (int idx = tid; idx < 64 * 128; idx += NT) {
        int i = idx >> 7, j = idx & 127;
        aug[i * 129 + j] = (j < 64) ? g_Cm[i * 64 + j] : ((j - 64 == i) ? 1.0f : 0.0f);
    }
    __syncthreads();
    for (int k = 0; k < 64; k++) {
        float pinv = 1.0f / aug[k * 129 + k];
        __syncthreads();
        for (int j = tid; j < 128; j += NT) aug[k * 129 + j] *= pinv;
        for (int i = tid; i < 64;  i += NT) colk[i] = aug[i * 129 + k];
        __syncthreads();
        for (int idx = tid; idx < 64 * 128; idx += NT) {
            int i = idx >> 7, j = idx & 127;
            if (i != k) aug[i * 129 + j] -= colk[i] * aug[k * 129 + j];
        }
        __syncthreads();
    }
    for (int idx = tid; idx < 64 * 64; idx += NT)
        g_Inv[idx] = aug[(idx >> 6) * 129 + 64 + (idx & 63)];
}

// ---------------- CL1: opA (1024 blocks) ∪ gram0 (64 blocks), 128 threads ----------------
// opA: Acc[p] += sum_r sum_col Mt[r, adj(p,col)] * N[r,col], k-split, 4h x 2w per thread.
__global__ void __launch_bounds__(128) k_cl1(const float* __restrict__ pa,
                                             const float* __restrict__ pg) {
    __shared__ float buf[6800];
    int tid = threadIdx.x;
    int b = blockIdx.x;
    if (b >= 1024) { gram_role(buf, 0, b - 1024, pa, pg, 128, tid); return; }

    int hc = b & 7, kk = (b >> 3) & 1, r = b >> 4;
    float* Msx = buf;            // 2 planes x 43 rows x 64
    float* Fs  = buf + 5504;     // 1296
    const float* Mrow = g_Mt + r * MDIM;
    for (int idx = tid; idx < 5504; idx += 128) {
        int cc = idx / 2752; int rem = idx - cc * 2752;
        int lr = rem >> 6;    int w = rem & 63;
        Msx[idx] = Mrow[cc * 4096 + ((hc * 8 + lr) & 63) * 64 + w];
    }
    for (int idx = tid; idx < 1296; idx += 128)
        Fs[idx] = g_N[r * KC + kk * 1296 + idx];
    __syncthreads();

    int w1 = tid & 31; int gb = tid >> 5; int c = gb & 1; int hsub = gb >> 1;
    int base = ((c + kk) & 1) * 2752 + hsub * 4 * 64;
    float aA0=0.f,aA1=0.f,aA2=0.f,aA3=0.f,aB0=0.f,aB1=0.f,aB2=0.f,aB3=0.f;
    for (int j = 0; j < KK2; j++) {
        int wcA = (w1 + j) & 63; int wcB = (wcA + 32) & 63;
        const float* mpA = Msx + base + wcA;
        const float* mpB = Msx + base + wcB;
        const float* fp  = Fs + j * KK1;
        float A0 = mpA[0], A1 = mpA[64], A2 = mpA[128];
        float B0 = mpB[0], B1 = mpB[64], B2 = mpB[128];
        #pragma unroll
        for (int i = 0; i < KK1; i++) {
            float A3 = mpA[(i + 3) * 64];
            float B3 = mpB[(i + 3) * 64];
            float f  = fp[i];
            aA0 += A0 * f; aA1 += A1 * f; aA2 += A2 * f; aA3 += A3 * f;
            aB0 += B0 * f; aB1 += B1 * f; aB2 += B2 * f; aB3 += B3 * f;
            A0 = A1; A1 = A2; A2 = A3;
            B0 = B1; B1 = B2; B2 = B3;
        }
    }
    int pb = c * 4096 + (hc * 8 + hsub * 4) * 64;
    atomicAdd(&g_Acc[pb + 0*64 + w1], aA0);
    atomicAdd(&g_Acc[pb + 1*64 + w1], aA1);
    atomicAdd(&g_Acc[pb + 2*64 + w1], aA2);
    atomicAdd(&g_Acc[pb + 3*64 + w1], aA3);
    atomicAdd(&g_Acc[pb + 0*64 + w1 + 32], aB0);
    atomicAdd(&g_Acc[pb + 1*64 + w1 + 32], aB1);
    atomicAdd(&g_Acc[pb + 2*64 + w1 + 32], aB2);
    atomicAdd(&g_Acc[pb + 3*64 + w1 + 32], aB3);
}

// ---------------- CL2: elementwise L/S update + Acc reset + T zero (+ final out) ----------
__global__ void __launch_bounds__(256) k_cl2(const float* __restrict__ img,
                                             const float* __restrict__ pg,
                                             const float* __restrict__ pb,
                                             int final, float* __restrict__ out) {
    int p = blockIdx.x * 256 + threadIdx.x;     // grid = 32 -> p < 8192
    float gam = *pg, bet = *pb;
    float akadj = g_Acc[p] * (1.0f / (float)KC);
    float ln = (img[p] - g_S[p] + gam * akadj) / (gam + 1.0f);
    ln = fminf(fmaxf(ln, 0.0f), 1.0f);
    g_L[p] = ln;
    g_S[p] = (img[p] - ln) / (bet + 1.0f);
    g_Acc[p] = 0.0f;
    if (final) out[p] = ln;
    for (int t = p; t < MK * KC; t += MDIM) g_T[t] = 0.0f;
}

// ---------------- CL3: opB (1024 blocks) ∪ inv0 (1 block), 128 threads ----------------
// opB: GtP[k*4+jg][r, p=(c,h,w)] = sum_{j in grp, i} N[r,(k,j,i)] * L[(c-k),(h-i),(w-j)]
__global__ void __launch_bounds__(128) k_cl3() {
    __shared__ float buf[9408];
    int tid = threadIdx.x;
    int b = blockIdx.x;
    if (b >= 1024) { inv_role(buf, 128, tid); return; }

    int jg = b & 3, kk = (b >> 2) & 1, c = (b >> 3) & 1, h = b >> 4;
    float* Lx = buf;             // 64 x 73
    float* Ns = buf + 4672;      // 2 x (64 x 37)
    int cs = (c + kk) & 1;
    int j0 = jg * 9;
    for (int idx = tid; idx < 4672; idx += 128) {
        int hh = idx / 73; int t = idx - hh * 73;
        Lx[idx] = g_L[cs * 4096 + hh * 64 + ((t + 56 - j0) & 63)];
    }
    const float* Nb = g_N + kk * 1296;
    for (int idx = tid; idx < 2304; idx += 128) {
        int rr = idx / 36; int ii = idx - rr * 36;
        Ns[rr * 37 + ii] = Nb[rr * KC + j0 * 36 + ii];
    }
    __syncthreads();

    int wq = tid & 7; int rg = tid >> 3; int r0 = rg * 4;
    float acc[4][8];
    #pragma unroll
    for (int u = 0; u < 4; u++)
        #pragma unroll
        for (int s = 0; s < 8; s++) acc[u][s] = 0.f;

    for (int jj = 0; jj < 9; jj++) {
        float* cur = Ns + (jj & 1) * 2368;
        float* nxt = Ns + ((jj + 1) & 1) * 2368;
        if (jj < 8) {
            for (int idx = tid; idx < 2304; idx += 128) {
                int rr = idx / 36; int ii = idx - rr * 36;
                cp_async4(nxt + rr * 37 + ii, Nb + rr * KC + (j0 + jj + 1) * 36 + ii);
            }
            asm volatile("cp.async.commit_group;");
        }
        int off = wq + 8 - jj;
        #pragma unroll
        for (int i = 0; i < KK1; i++) {
            const float* lp = Lx + ((h - i) & 63) * 73 + off;
            float l0 = lp[0],  l1 = lp[8],  l2 = lp[16], l3 = lp[24];
            float l4 = lp[32], l5 = lp[40], l6 = lp[48], l7 = lp[56];
            float f0 = cur[(r0    ) * 37 + i];
            float f1 = cur[(r0 + 1) * 37 + i];
            float f2 = cur[(r0 + 2) * 37 + i];
            float f3 = cur[(r0 + 3) * 37 + i];
            acc[0][0]+=f0*l0; acc[0][1]+=f0*l1; acc[0][2]+=f0*l2; acc[0][3]+=f0*l3;
            acc[0][4]+=f0*l4; acc[0][5]+=f0*l5; acc[0][6]+=f0*l6; acc[0][7]+=f0*l7;
            acc[1][0]+=f1*l0; acc[1][1]+=f1*l1; acc[1][2]+=f1*l2; acc[1][3]+=f1*l3;
            acc[1][4]+=f1*l4; acc[1][5]+=f1*l5; acc[1][6]+=f1*l6; acc[1][7]+=f1*l7;
            acc[2][0]+=f2*l0; acc[2][1]+=f2*l1; acc[2][2]+=f2*l2; acc[2][3]+=f2*l3;
            acc[2][4]+=f2*l4; acc[2][5]+=f2*l5; acc[2][6]+=f2*l6; acc[2][7]+=f2*l7;
            acc[3][0]+=f3*l0; acc[3][1]+=f3*l1; acc[3][2]+=f3*l2; acc[3][3]+=f3*l3;
            acc[3][4]+=f3*l4; acc[3][5]+=f3*l5; acc[3][6]+=f3*l6; acc[3][7]+=f3*l7;
        }
        if (jj < 8) asm volatile("cp.async.wait_group 0;");
        __syncthreads();
    }
    float* GP = g_GtP + (kk * 4 + jg) * (MK * MDIM);
    int pb = c * 4096 + h * 64 + wq;
    #pragma unroll
    for (int u = 0; u < 4; u++)
        #pragma unroll
        for (int s = 0; s < 8; s++)
            GP[(r0 + u) * MDIM + pb + 8 * s] = acc[u][s];
}

// ---------------- role: opC  T[r,col] += sum_{c,h,w} L[c,h,w] * Mt[r, adj] (NT=256) -------
__device__ void opc_role(float* buf, int r, int hq, int tid) {
    float* Mtx = buf;             // 2 x 6480 (rows pitch 101)
    float* Lsm = buf + 12960;     // 2 x 16 x 65
    const float* Mrow = g_Mt + r * MDIM;
    for (int idx = tid; idx < 2 * 6464; idx += 256) {
        int cs = idx / 6464; int rem = idx - cs * 6464;
        int hh = rem / 101;  int t = rem - hh * 101;
        Mtx[cs * 6480 + hh * 101 + t] = Mrow[cs * 4096 + hh * 64 + ((t >= 64) ? t - 64 : t)];
    }
    for (int idx = tid; idx < 2048; idx += 256) {
        int cc = idx >> 10; int hl = (idx >> 6) & 15; int w = idx & 63;
        Lsm[(cc * 16 + hl) * 65 + w] = g_L[cc * 4096 + (hq * 16 + hl) * 64 + w];
    }
    __syncthreads();

    int warp = tid >> 5, lane = tid & 31;
    int c = lane >> 4, hl = lane & 15;
    int h = hq * 16 + hl;
    const float* lrow = Lsm + (c * 16 + hl) * 65;

    for (int kp = warp; kp < 72; kp += 8) {
        int k = (kp >= 36) ? 1 : 0;
        int i = kp - k * 36;
        int cs = (c + k) & 1;
        int hs = (h + i) & 63;
        const float* mrow = Mtx + cs * 6480 + hs * 101;

        float acc[36];
        #pragma unroll
        for (int t = 0; t < 36; t++) acc[t] = 0.f;
        float win[35];
        #pragma unroll
        for (int t = 0; t < 35; t++) win[t] = mrow[t];

        #pragma unroll
        for (int w = 0; w < 64; w++) {
            float lv = lrow[w];
            float nv = mrow[w + 35];
            #pragma unroll
            for (int t = 0; t < 35; t++) acc[t] += lv * win[t];
            acc[35] += lv * nv;
            #pragma unroll
            for (int t = 0; t < 34; t++) win[t] = win[t + 1];
            win[34] = nv;
        }

        int colb = r * KC + k * (KK2 * KK1) + i;
        #pragma unroll
        for (int jj = 0; jj < 36; jj++) {
            float s = acc[jj];
            s += __shfl_xor_sync(0xffffffffu, s, 16);
            s += __shfl_xor_sync(0xffffffffu, s, 8);
            s += __shfl_xor_sync(0xffffffffu, s, 4);
            s += __shfl_xor_sync(0xffffffffu, s, 2);
            s += __shfl_xor_sync(0xffffffffu, s, 1);
            if (lane == (jj & 31)) atomicAdd(&g_T[colb + jj * 36], s);
        }
    }
}

// ---------------- CL5/CL6: opC half (128) ∪ {gram1 (64) | inv1 (1)}, 256 threads ---------
__global__ void __launch_bounds__(256) k_cl56(int mode, const float* __restrict__ pa,
                                              const float* __restrict__ pg) {
    __shared__ float buf[15040];
    int tid = threadIdx.x;
    int b = blockIdx.x;
    if (b < 128) {
        opc_role(buf, b & 63, (mode ? 2 : 0) + (b >> 6), tid);
    } else if (mode == 0) {
        gram_role(buf, 1, b - 128, pa, pg, 256, tid);
    } else {
        inv_role(buf, 256, tid);
    }
}

// ---------------- small mm: out = 2*gamma * g_Inv @ X ----------------
__global__ void __launch_bounds__(256) k_smallmm(int which, const float* __restrict__ pg) {
    __shared__ float As[4096];
    __shared__ float Xs[4096];
    float* out = which ? g_N : g_Mt;
    int Kcols  = which ? KC  : MDIM;
    int tid = threadIdx.x;
    int tx = tid & 63, ty = tid >> 6;
    int cb = blockIdx.x * 64;
    for (int i = tid; i < 4096; i += 256) As[i] = g_Inv[i];
    for (int i = tid; i < 4096; i += 256) {
        int q = i >> 6, cc = cb + (i & 63);
        float v = 0.f;
        if (cc < Kcols) {
            if (which) v = g_T[q * KC + cc];
            else {
                #pragma unroll
                for (int s = 0; s < 8; s++) v += g_GtP[s * (MK * MDIM) + q * MDIM + cc];
            }
        }
        Xs[i] = v;
    }
    __syncthreads();
    float acc[16];
    #pragma unroll
    for (int u = 0; u < 16; u++) acc[u] = 0.f;
    for (int q = 0; q < 64; q++) {
        float xv = Xs[q * 64 + tx];
        #pragma unroll
        for (int u = 0; u < 16; u++)
            acc[u] += As[(ty * 16 + u) * 64 + q] * xv;
    }
    int col = cb + tx;
    if (col < Kcols) {
        float sc = 2.0f * (*pg);
        #pragma unroll
        for (int u = 0; u < 16; u++)
            out[(ty * 16 + u) * Kcols + col] = sc * acc[u];
    }
}

// =====================================================================================
extern "C" void kernel_launch(void* const* d_in, const int* in_sizes, int n_in,
                              void* d_out, int out_size) {
    const float* img = (const float*)d_in[0];
    const float* S0  = (const float*)d_in[1];
    const float* pa  = (const float*)d_in[2];   // alpha
    const float* pb  = (const float*)d_in[3];   // beta
    const float* pg  = (const float*)d_in[4];   // gamma
    float* out = (float*)d_out;
    (void)in_sizes; (void)n_in; (void)out_size;

    k_init<<<(MK * MDIM + 255) / 256, 256>>>(img, S0);

    for (int it = 0; it < NSTEPS; it++) {
        int last = (it == NSTEPS - 1);
        k_cl1<<<last ? 1024 : 1088, 128>>>(pa, pg);          // opA (+ gram0)
        k_cl2<<<32, 256>>>(img, pg, pb, last, out);          // L/S update (+zeros, +out)
        if (!last) {
            k_cl3<<<1025, 128>>>();                          // opB + inv0
            k_smallmm<<<MDIM / 64, 256>>>(0, pg);            // Mt = 2g Inv @ sum(GtP)
            k_cl56<<<192, 256>>>(0, pa, pg);                 // opC(hq0,1) + gram1
            k_cl56<<<129, 256>>>(1, pa, pg);                 // opC(hq2,3) + inv1
            k_smallmm<<<(KC + 63) / 64, 256>>>(1, pg);       // N = 2g Inv @ T
        }
    }
}

// round 9
// speedup vs baseline: 2.3370x; 1.0664x over previous
#include <cuda_runtime.h>

// Problem constants (B=1, C=2, H=W=64, k1=k2=36, k3=2, iters=6 -> 5 steps)
#define HW    4096
#define MDIM  8192
#define MK    64
#define KK1   36
#define KK2   36
#define KK3   2
#define KC    2592
#define NSTEPS 5
#define NT_SLAB 2432            // padded (r,j) slab: 64*37=2368 used, 19*128 copied

// -------- persistent device state --------
__device__ float g_L  [MDIM];
__device__ float g_S  [MDIM];
__device__ float g_Mt [MK * MDIM];       // M^T : [r][p]
__device__ float g_N  [MK * KC];         // N   : [r][col]
__device__ float g_Nt [72 * NT_SLAB];    // N transposed: [(k*36+i)][r*37+j]
__device__ float g_GtP[8 * MK * MDIM];   // opB partials per (k,ig)
__device__ float g_T  [MK * KC];         // M^T @ AkL
__device__ float g_Cm [MK * MK];
__device__ float g_Inv[MK * MK];
__device__ float g_Acc[MDIM];

__device__ __forceinline__ void cp_async4(void* sm, const void* gm) {
    unsigned sa = (unsigned)__cvta_generic_to_shared(sm);
    asm volatile("cp.async.ca.shared.global [%0], [%1], 4;" :: "r"(sa), "l"(gm));
}

// ---------------- init: L=img, S=S0, Mt=eye, N=eye, Nt=eye, Acc=0 ----------------
__global__ void k_init(const float* __restrict__ img, const float* __restrict__ S0) {
    int idx = blockIdx.x * 256 + threadIdx.x;
    if (idx < MDIM) { g_L[idx] = img[idx]; g_S[idx] = S0[idx]; g_Acc[idx] = 0.0f; }
    if (idx < MK * MDIM) {
        int r = idx >> 13, p = idx & (MDIM - 1);
        g_Mt[idx] = (p == r) ? 1.0f : 0.0f;
    }
    if (idx < MK * KC) {
        int r = idx / KC, c = idx - r * KC;
        g_N[idx] = (c == r) ? 1.0f : 0.0f;
    }
    if (idx < 72 * NT_SLAB) {
        int slab = idx / NT_SLAB; int slot = idx - slab * NT_SLAB;
        int kk = slab / 36; int i = slab - kk * 36;
        int r = slot / 37;  int j = slot - r * 37;
        float v = 0.0f;
        if (j < 36 && r < 64) {
            int col = (kk * 36 + j) * 36 + i;
            if (col == r) v = 1.0f;
        }
        g_Nt[idx] = v;
    }
}

// ---------------- role: gram  g_Cm = alpha*I + 2*gamma * X X^T ----------------
__device__ void gram_role(float* buf, int which, int a,
                          const float* pa, const float* pg, int NT, int tid) {
    const float* X = which ? g_Mt : g_N;
    int K = which ? MDIM : KC;
    for (int i = tid; i < K; i += NT) buf[i] = X[a * K + i];
    __syncthreads();
    int warp = tid >> 5, lane = tid & 31, nw = NT >> 5;
    for (int b = warp; b < MK; b += nw) {
        const float* xb = X + b * K;
        float s = 0.f;
        for (int kk = lane; kk < K; kk += 32) s += buf[kk] * xb[kk];
        #pragma unroll
        for (int o = 16; o; o >>= 1) s += __shfl_xor_sync(0xffffffffu, s, o);
        if (lane == 0) {
            float v = 2.0f * (*pg) * s;
            if (a == b) v += *pa;
            g_Cm[a * MK + b] = v;
        }
    }
}

// ---------------- role: 64x64 SPD inverse (Gauss-Jordan), generic NT ----------------
__device__ void inv_role(float* buf, int NT, int tid) {
    float* aug  = buf;            // 64*129 = 8256
    float* colk = buf + 8256;     // 64
    for (int idx = tid; idx < 64 * 128; idx += NT) {
        int i = idx >> 7, j = idx & 127;
        aug[i * 129 + j] = (j < 64) ? g_Cm[i * 64 + j] : ((j - 64 == i) ? 1.0f : 0.0f);
    }
    __syncthreads();
    for (int k = 0; k < 64; k++) {
        float pinv = 1.0f / aug[k * 129 + k];
        __syncthreads();
        for (int j = tid; j < 128; j += NT) aug[k * 129 + j] *= pinv;
        for (int i = tid; i < 64;  i += NT) colk[i] = aug[i * 129 + k];
        __syncthreads();
        for (int idx = tid; idx < 64 * 128; idx += NT) {
            int i = idx >> 7, j = idx & 127;
            if (i != k) aug[i * 129 + j] -= colk[i] * aug[k * 129 + j];
        }
        __syncthreads();
    }
    for (int idx = tid; idx < 64 * 64; idx += NT)
        g_Inv[idx] = aug[(idx >> 6) * 129 + 64 + (idx & 63)];
}

// ---------------- CL1: opA (1024 blocks) ∪ gram0 (64 blocks), 128 threads ----------------
// opA: Acc[p=(c,h,w)] += sum_r,k,j,i Mt[r,(c+k),(h+i),(w+j)] * N[r,(k,j,i)]
// block = (hc 0..3, jh 0..1, kk 0..1, r 0..63); thread = (w 0..63, c 0..1).
// 16 h-outputs via 16-tall register window sliding over i. 1 M-LDS + 1 F-LDS per 16 FFMA.
__global__ void __launch_bounds__(128) k_cl1(const float* __restrict__ pa,
                                             const float* __restrict__ pg) {
    __shared__ float buf[7304];          // Msx 2*52*64 = 6656 | Fs 648
    int tid = threadIdx.x;
    int b = blockIdx.x;
    if (b >= 1024) { gram_role(buf, 0, b - 1024, pa, pg, 128, tid); return; }

    int hc = b & 3, jh = (b >> 2) & 1, kk = (b >> 3) & 1, r = b >> 4;
    int h0 = hc * 16;
    float* Msx = buf;                    // [cc][lr<52][w]
    float* Fs  = buf + 6656;             // 18 j x 36 i
    const float* Mrow = g_Mt + r * MDIM;
    for (int idx = tid; idx < 6656; idx += 128) {
        int cc = idx / 3328; int rem = idx - cc * 3328;
        int lr = rem >> 6;   int w = rem & 63;
        Msx[idx] = Mrow[cc * 4096 + ((h0 + lr) & 63) * 64 + w];
    }
    const float* Fg = g_N + r * KC + kk * 1296 + jh * 648;
    for (int idx = tid; idx < 648; idx += 128) Fs[idx] = Fg[idx];
    __syncthreads();

    int w1 = tid & 63, c = tid >> 6;
    int base = ((c + kk) & 1) * 3328;
    int jbase = jh * 18;
    float acc[16];
    #pragma unroll
    for (int s = 0; s < 16; s++) acc[s] = 0.f;

    for (int jp = 0; jp < 18; jp++) {
        int wc = (w1 + jbase + jp) & 63;
        const float* mp = Msx + base + wc;
        const float* fp = Fs + jp * 36;
        float W[16];
        #pragma unroll
        for (int s = 0; s < 16; s++) W[s] = mp[s * 64];
        #pragma unroll
        for (int i = 0; i < 36; i++) {
            float f = fp[i];
            #pragma unroll
            for (int s = 0; s < 16; s++) acc[s] += W[s] * f;
            if (i < 35) {
                #pragma unroll
                for (int s = 0; s < 15; s++) W[s] = W[s + 1];
                W[15] = mp[(16 + i) * 64];
            }
        }
    }
    int pb = c * 4096 + h0 * 64 + w1;
    #pragma unroll
    for (int s = 0; s < 16; s++)
        atomicAdd(&g_Acc[pb + s * 64], acc[s]);
}

// ---------------- CL2: elementwise L/S update + Acc reset + T zero (+ final out) ----------
__global__ void __launch_bounds__(256) k_cl2(const float* __restrict__ img,
                                             const float* __restrict__ pg,
                                             const float* __restrict__ pb,
                                             int final, float* __restrict__ out) {
    int p = blockIdx.x * 256 + threadIdx.x;     // grid = 32 -> p < 8192
    float gam = *pg, bet = *pb;
    float akadj = g_Acc[p] * (1.0f / (float)KC);
    float ln = (img[p] - g_S[p] + gam * akadj) / (gam + 1.0f);
    ln = fminf(fmaxf(ln, 0.0f), 1.0f);
    g_L[p] = ln;
    g_S[p] = (img[p] - ln) / (bet + 1.0f);
    g_Acc[p] = 0.0f;
    if (final) out[p] = ln;
    for (int t = p; t < MK * KC; t += MDIM) g_T[t] = 0.0f;
}

// ---------------- CL3: opB (1024 blocks) ∪ inv0 (1 block), 128 threads ----------------
// opB: GtP[kk*4+ig][r, p=(c,h,w)] = sum_{i in grp, j} Nt[kk][i][r][j] * L[(c-k),(h-i),(w-j)]
// block = (ig 0..3, kk 0..1, c 0..1, h 0..63); thread = (wq 0..7 -> 8 w, rg 0..15 -> 4 r).
// 8-wide w register window sliding over j: per j = 32 FFMA + 1 L-LDS + 4 N-LDS.
__global__ void __launch_bounds__(128) k_cl3() {
    __shared__ float buf[9408];          // Lx 909 (+pad) | Ns 2 x 2432 @ 912 ; inv needs 8320
    int tid = threadIdx.x;
    int b = blockIdx.x;
    if (b >= 1024) { inv_role(buf, 128, tid); return; }

    int ig = b & 3, kk = (b >> 2) & 1, c = (b >> 3) & 1, h = b >> 4;
    int i0 = ig * 9;
    int cs = (c + kk) & 1;
    float* Lx  = buf;                    // [il<9][t<101]: L[cs,(h-i0-il)&63,(t+29)&63]
    float* Ns0 = buf + 912;
    for (int idx = tid; idx < 909; idx += 128) {
        int il = idx / 101; int t = idx - il * 101;
        Lx[idx] = g_L[cs * 4096 + ((h - i0 - il) & 63) * 64 + ((t + 29) & 63)];
    }
    const float* Ntb = g_Nt + (kk * 36 + i0) * NT_SLAB;
    for (int idx = tid; idx < NT_SLAB; idx += 128) Ns0[idx] = Ntb[idx];
    __syncthreads();

    int wq = tid & 7, rg = tid >> 3;
    int w0 = wq * 8, r0 = rg * 4;
    float acc[4][8];
    #pragma unroll
    for (int u = 0; u < 4; u++)
        #pragma unroll
        for (int s = 0; s < 8; s++) acc[u][s] = 0.f;

    for (int il = 0; il < 9; il++) {
        float* cur = Ns0 + (il & 1) * NT_SLAB;
        float* nxt = Ns0 + ((il + 1) & 1) * NT_SLAB;
        if (il < 8) {
            const float* src = Ntb + (il + 1) * NT_SLAB;
            #pragma unroll
            for (int q = 0; q < 19; q++)
                cp_async4(nxt + tid + q * 128, src + tid + q * 128);
            asm volatile("cp.async.commit_group;");
        }
        const float* lrow = Lx + il * 101;
        float W[8];
        #pragma unroll
        for (int s = 0; s < 8; s++) W[s] = lrow[w0 + s + 35];
        #pragma unroll
        for (int j = 0; j < 36; j++) {
            float f0 = cur[(r0 + 0) * 37 + j];
            float f1 = cur[(r0 + 1) * 37 + j];
            float f2 = cur[(r0 + 2) * 37 + j];
            float f3 = cur[(r0 + 3) * 37 + j];
            #pragma unroll
            for (int s = 0; s < 8; s++) {
                acc[0][s] += f0 * W[s];
                acc[1][s] += f1 * W[s];
                acc[2][s] += f2 * W[s];
                acc[3][s] += f3 * W[s];
            }
            if (j < 35) {
                #pragma unroll
                for (int s = 7; s > 0; s--) W[s] = W[s - 1];
                W[0] = lrow[w0 + 34 - j];
            }
        }
        if (il < 8) asm volatile("cp.async.wait_group 0;");
        __syncthreads();
    }
    float* GP = g_GtP + (kk * 4 + ig) * (MK * MDIM);
    int pb = c * 4096 + h * 64 + w0;
    #pragma unroll
    for (int u = 0; u < 4; u++) {
        float4 v0 = make_float4(acc[u][0], acc[u][1], acc[u][2], acc[u][3]);
        float4 v1 = make_float4(acc[u][4], acc[u][5], acc[u][6], acc[u][7]);
        *reinterpret_cast<float4*>(&GP[(r0 + u) * MDIM + pb])     = v0;
        *reinterpret_cast<float4*>(&GP[(r0 + u) * MDIM + pb + 4]) = v1;
    }
}

// ---------------- role: opC  T[r,col] += sum_{c,h,w} L[c,h,w] * Mt[r, adj] (NT=256) -------
__device__ void opc_role(float* buf, int r, int hq, int tid) {
    float* Mtx = buf;             // 2 x 6480 (rows pitch 101)
    float* Lsm = buf + 12960;     // 2 x 16 x 65
    const float* Mrow = g_Mt + r * MDIM;
    for (int idx = tid; idx < 2 * 6464; idx += 256) {
        int cs = idx / 6464; int rem = idx - cs * 6464;
        int hh = rem / 101;  int t = rem - hh * 101;
        Mtx[cs * 6480 + hh * 101 + t] = Mrow[cs * 4096 + hh * 64 + ((t >= 64) ? t - 64 : t)];
    }
    for (int idx = tid; idx < 2048; idx += 256) {
        int cc = idx >> 10; int hl = (idx >> 6) & 15; int w = idx & 63;
        Lsm[(cc * 16 + hl) * 65 + w] = g_L[cc * 4096 + (hq * 16 + hl) * 64 + w];
    }
    __syncthreads();

    int warp = tid >> 5, lane = tid & 31;
    int c = lane >> 4, hl = lane & 15;
    int h = hq * 16 + hl;
    const float* lrow = Lsm + (c * 16 + hl) * 65;

    for (int kp = warp; kp < 72; kp += 8) {
        int k = (kp >= 36) ? 1 : 0;
        int i = kp - k * 36;
        int cs = (c + k) & 1;
        int hs = (h + i) & 63;
        const float* mrow = Mtx + cs * 6480 + hs * 101;

        float acc[36];
        #pragma unroll
        for (int t = 0; t < 36; t++) acc[t] = 0.f;
        float win[35];
        #pragma unroll
        for (int t = 0; t < 35; t++) win[t] = mrow[t];

        #pragma unroll
        for (int w = 0; w < 64; w++) {
            float lv = lrow[w];
            float nv = mrow[w + 35];
            #pragma unroll
            for (int t = 0; t < 35; t++) acc[t] += lv * win[t];
            acc[35] += lv * nv;
            #pragma unroll
            for (int t = 0; t < 34; t++) win[t] = win[t + 1];
            win[34] = nv;
        }

        int colb = r * KC + k * (KK2 * KK1) + i;
        #pragma unroll
        for (int jj = 0; jj < 36; jj++) {
            float s = acc[jj];
            s += __shfl_xor_sync(0xffffffffu, s, 16);
            s += __shfl_xor_sync(0xffffffffu, s, 8);
            s += __shfl_xor_sync(0xffffffffu, s, 4);
            s += __shfl_xor_sync(0xffffffffu, s, 2);
            s += __shfl_xor_sync(0xffffffffu, s, 1);
            if (lane == (jj & 31)) atomicAdd(&g_T[colb + jj * 36], s);
        }
    }
}

// ---------------- CL5/CL6: opC half (128) ∪ {gram1 (64) | inv1 (1)}, 256 threads ---------
__global__ void __launch_bounds__(256) k_cl56(int mode, const float* __restrict__ pa,
                                              const float* __restrict__ pg) {
    __shared__ float buf[15040];
    int tid = threadIdx.x;
    int b = blockIdx.x;
    if (b < 128) {
        opc_role(buf, b & 63, (mode ? 2 : 0) + (b >> 6), tid);
    } else if (mode == 0) {
        gram_role(buf, 1, b - 128, pa, pg, 256, tid);
    } else {
        inv_role(buf, 256, tid);
    }
}

// ---------------- small mm: out = 2*gamma * g_Inv @ X  (+ Nt transpose for which=1) -------
__global__ void __launch_bounds__(256) k_smallmm(int which, const float* __restrict__ pg) {
    __shared__ float As[4096];
    __shared__ float Xs[4096];
    float* out = which ? g_N : g_Mt;
    int Kcols  = which ? KC  : MDIM;
    int tid = threadIdx.x;
    int tx = tid & 63, ty = tid >> 6;
    int cb = blockIdx.x * 64;
    for (int i = tid; i < 4096; i += 256) As[i] = g_Inv[i];
    for (int i = tid; i < 4096; i += 256) {
        int q = i >> 6, cc = cb + (i & 63);
        float v = 0.f;
        if (cc < Kcols) {
            if (which) v = g_T[q * KC + cc];
            else {
                #pragma unroll
                for (int s = 0; s < 8; s++) v += g_GtP[s * (MK * MDIM) + q * MDIM + cc];
            }
        }
        Xs[i] = v;
    }
    __syncthreads();
    float acc[16];
    #pragma unroll
    for (int u = 0; u < 16; u++) acc[u] = 0.f;
    for (int q = 0; q < 64; q++) {
        float xv = Xs[q * 64 + tx];
        #pragma unroll
        for (int u = 0; u < 16; u++)
            acc[u] += As[(ty * 16 + u) * 64 + q] * xv;
    }
    int col = cb + tx;
    if (col < Kcols) {
        float sc = 2.0f * (*pg);
        #pragma unroll
        for (int u = 0; u < 16; u++)
            out[(ty * 16 + u) * Kcols + col] = sc * acc[u];
        if (which) {
            int k2 = col / 1296; int rem = col - k2 * 1296;
            int j  = rem / 36;   int i2 = rem - j * 36;
            float* nt = g_Nt + (k2 * 36 + i2) * NT_SLAB + j;
            #pragma unroll
            for (int u = 0; u < 16; u++)
                nt[(ty * 16 + u) * 37] = sc * acc[u];
        }
    }
}

// =====================================================================================
extern "C" void kernel_launch(void* const* d_in, const int* in_sizes, int n_in,
                              void* d_out, int out_size) {
    const float* img = (const float*)d_in[0];
    const float* S0  = (const float*)d_in[1];
    const float* pa  = (const float*)d_in[2];   // alpha
    const float* pb  = (const float*)d_in[3];   // beta
    const float* pg  = (const float*)d_in[4];   // gamma
    float* out = (float*)d_out;
    (void)in_sizes; (void)n_in; (void)out_size;

    k_init<<<(MK * MDIM + 255) / 256, 256>>>(img, S0);

    for (int it = 0; it < NSTEPS; it++) {
        int last = (it == NSTEPS - 1);
        k_cl1<<<last ? 1024 : 1088, 128>>>(pa, pg);          // opA (+ gram0)
        k_cl2<<<32, 256>>>(img, pg, pb, last, out);          // L/S update (+zeros, +out)
        if (!last) {
            k_cl3<<<1025, 128>>>();                          // opB + inv0
            k_smallmm<<<MDIM / 64, 256>>>(0, pg);            // Mt = 2g Inv @ sum(GtP)
            k_cl56<<<192, 256>>>(0, pa, pg);                 // opC(hq0,1) + gram1
            k_cl56<<<129, 256>>>(1, pa, pg);                 // opC(hq2,3) + inv1
            k_smallmm<<<(KC + 63) / 64, 256>>>(1, pg);       // N = 2g Inv @ T (+ Nt)
        }
    }
}

// round 12
// speedup vs baseline: 2.4469x; 1.0470x over previous
#include <cuda_runtime.h>

// Problem constants (B=1, C=2, H=W=64, k1=k2=36, k3=2, iters=6 -> 5 steps)
#define HW    4096
#define MDIM  8192
#define MK    64
#define KK1   36
#define KK2   36
#define KK3   2
#define KC    2592
#define NSTEPS 5
#define NT_SLAB 2432            // padded (r,j) slab: 64*37=2368 used, 19*128 copied

// -------- persistent device state --------
__device__ float g_L  [MDIM];
__device__ float g_S  [MDIM];
__device__ float g_Mt [MK * MDIM];       // M^T : [r][p]
__device__ float g_N  [MK * KC];         // N   : [r][col]
__device__ float g_Nt [72 * NT_SLAB];    // N transposed: [(k*36+i)][r*37+j]
__device__ float g_GtP[8 * MK * MDIM];   // opB partials per (k,ig)
__device__ float g_T  [MK * KC];         // M^T @ AkL
__device__ float g_Cm [MK * MK];
__device__ float g_Inv[MK * MK];
__device__ float g_Acc[MDIM];

__device__ __forceinline__ void cp_async4(void* sm, const void* gm) {
    unsigned sa = (unsigned)__cvta_generic_to_shared(sm);
    asm volatile("cp.async.ca.shared.global [%0], [%1], 4;" :: "r"(sa), "l"(gm));
}

// ---------------- init: L=img, S=S0, Mt=eye, N=eye, Nt=eye, Acc=0 ----------------
__global__ void k_init(const float* __restrict__ img, const float* __restrict__ S0) {
    int idx = blockIdx.x * 256 + threadIdx.x;
    if (idx < MDIM) { g_L[idx] = img[idx]; g_S[idx] = S0[idx]; g_Acc[idx] = 0.0f; }
    if (idx < MK * MDIM) {
        int r = idx >> 13, p = idx & (MDIM - 1);
        g_Mt[idx] = (p == r) ? 1.0f : 0.0f;
    }
    if (idx < MK * KC) {
        int r = idx / KC, c = idx - r * KC;
        g_N[idx] = (c == r) ? 1.0f : 0.0f;
    }
    if (idx < 72 * NT_SLAB) {
        int slab = idx / NT_SLAB; int slot = idx - slab * NT_SLAB;
        int kk = slab / 36; int i = slab - kk * 36;
        int r = slot / 37;  int j = slot - r * 37;
        float v = 0.0f;
        if (j < 36 && r < 64) {
            int col = (kk * 36 + j) * 36 + i;
            if (col == r) v = 1.0f;
        }
        g_Nt[idx] = v;
    }
}

// ---------------- role: gram  g_Cm = alpha*I + 2*gamma * X X^T ----------------
__device__ void gram_role(float* buf, int which, int a,
                          const float* pa, const float* pg, int NT, int tid) {
    const float* X = which ? g_Mt : g_N;
    int K = which ? MDIM : KC;
    for (int i = tid; i < K; i += NT) buf[i] = X[a * K + i];
    __syncthreads();
    int warp = tid >> 5, lane = tid & 31, nw = NT >> 5;
    for (int b = warp; b < MK; b += nw) {
        const float* xb = X + b * K;
        float s = 0.f;
        for (int kk = lane; kk < K; kk += 32) s += buf[kk] * xb[kk];
        #pragma unroll
        for (int o = 16; o; o >>= 1) s += __shfl_xor_sync(0xffffffffu, s, o);
        if (lane == 0) {
            float v = 2.0f * (*pg) * s;
            if (a == b) v += *pa;
            g_Cm[a * MK + b] = v;
        }
    }
}

// ---------------- role: 64x64 SPD inverse, IN-PLACE Gauss-Jordan (NR gaussj form) --------
// smem: a[64*65] + colk[64] = 4224 floats (16.9 KB)
__device__ void inv_role(float* buf, int NT, int tid) {
    float* a    = buf;            // 64 x 65 (pitch 65)
    float* colk = buf + 4160;
    for (int idx = tid; idx < 64 * 64; idx += NT)
        a[(idx >> 6) * 65 + (idx & 63)] = g_Cm[idx];
    __syncthreads();
    for (int k = 0; k < 64; k++) {
        float p = 1.0f / a[k * 65 + k];
        for (int i = tid; i < 64; i += NT) colk[i] = a[i * 65 + k];
        __syncthreads();
        for (int j = tid; j < 64; j += NT)
            a[k * 65 + j] = (j == k) ? p : a[k * 65 + j] * p;
        __syncthreads();
        for (int idx = tid; idx < 64 * 64; idx += NT) {
            int i = idx >> 6, j = idx & 63;
            if (i != k)
                a[i * 65 + j] = (j == k) ? -colk[i] * p
                                         : a[i * 65 + j] - colk[i] * a[k * 65 + j];
        }
        __syncthreads();
    }
    for (int idx = tid; idx < 64 * 64; idx += NT)
        g_Inv[idx] = a[(idx >> 6) * 65 + (idx & 63)];
}

// ---------------- CL1: opA only, 1024 blocks, single wave @7/SM ----------------
// opA: Acc[p=(c,h,w)] += sum_r,k,j,i Mt[r,(c+k),(h+i),(w+j)] * N[r,(k,j,i)]
// block = (hc 0..3, jh 0..1, kk 0..1, r 0..63); thread = (w 0..63, c 0..1).
// 16 h-outputs via 16-tall register window over i. smem 28.7 KB (51-row halo).
__global__ void __launch_bounds__(128, 7) k_cl1() {
    __shared__ float buf[7176];          // Msx 2*51*64 = 6528 | Fs 648
    int tid = threadIdx.x;
    int b = blockIdx.x;

    int hc = b & 3, jh = (b >> 2) & 1, kk = (b >> 3) & 1, r = b >> 4;
    int h0 = hc * 16;
    float* Msx = buf;                    // [cc][lr<51][w]
    float* Fs  = buf + 6528;             // 18 j x 36 i
    const float* Mrow = g_Mt + r * MDIM;
    for (int idx = tid; idx < 6528; idx += 128) {
        int cc = idx / 3264; int rem = idx - cc * 3264;
        int lr = rem >> 6;   int w = rem & 63;
        Msx[idx] = Mrow[cc * 4096 + ((h0 + lr) & 63) * 64 + w];
    }
    const float* Fg = g_N + r * KC + kk * 1296 + jh * 648;
    for (int idx = tid; idx < 648; idx += 128) Fs[idx] = Fg[idx];
    __syncthreads();

    int w1 = tid & 63, c = tid >> 6;
    int base = ((c + kk) & 1) * 3264;
    int jbase = jh * 18;
    float acc[16];
    #pragma unroll
    for (int s = 0; s < 16; s++) acc[s] = 0.f;

    for (int jp = 0; jp < 18; jp++) {
        int wc = (w1 + jbase + jp) & 63;
        const float* mp = Msx + base + wc;
        const float* fp = Fs + jp * 36;
        float W[16];
        #pragma unroll
        for (int s = 0; s < 16; s++) W[s] = mp[s * 64];
        #pragma unroll
        for (int i = 0; i < 36; i++) {
            float f = fp[i];
            #pragma unroll
            for (int s = 0; s < 16; s++) acc[s] += W[s] * f;
            if (i < 35) {
                #pragma unroll
                for (int s = 0; s < 15; s++) W[s] = W[s + 1];
                W[15] = mp[(16 + i) * 64];
            }
        }
    }
    int pb = c * 4096 + h0 * 64 + w1;
    #pragma unroll
    for (int s = 0; s < 16; s++)
        atomicAdd(&g_Acc[pb + s * 64], acc[s]);
}

// ---------------- CL2: elem (32 blocks) ∪ gram0 (64 blocks), 256 threads ----------------
__global__ void __launch_bounds__(256) k_cl2(const float* __restrict__ img,
                                             const float* __restrict__ pa,
                                             const float* __restrict__ pg,
                                             const float* __restrict__ pb,
                                             int final, float* __restrict__ out) {
    __shared__ float buf[2592];
    int tid = threadIdx.x;
    int b = blockIdx.x;
    if (b >= 32) { gram_role(buf, 0, b - 32, pa, pg, 256, tid); return; }

    int p = b * 256 + tid;               // p < 8192
    float gam = *pg, bet = *pb;
    float akadj = g_Acc[p] * (1.0f / (float)KC);
    float ln = (img[p] - g_S[p] + gam * akadj) / (gam + 1.0f);
    ln = fminf(fmaxf(ln, 0.0f), 1.0f);
    g_L[p] = ln;
    g_S[p] = (img[p] - ln) / (bet + 1.0f);
    g_Acc[p] = 0.0f;
    if (final) out[p] = ln;
    for (int t = p; t < MK * KC; t += MDIM) g_T[t] = 0.0f;
}

// ---------------- CL3: opB (1024 blocks) ∪ inv0 (1 block), single wave @7/SM ----------
// opB: GtP[kk*4+ig][r, p=(c,h,w)] = sum_{i in grp, j} Nt[kk][i][r][j] * L[(c-k),(h-i),(w-j)]
// block = (ig 0..3, kk 0..1, c 0..1, h 0..63); thread = (wq 0..7 -> 8 w, rg 0..15 -> 4 r).
// smem 23.1 KB: Lx 912 | Ns 2 x 2432.
__global__ void __launch_bounds__(128, 7) k_cl3() {
    __shared__ float buf[5776];
    int tid = threadIdx.x;
    int b = blockIdx.x;
    if (b >= 1024) { inv_role(buf, 128, tid); return; }

    int ig = b & 3, kk = (b >> 2) & 1, c = (b >> 3) & 1, h = b >> 4;
    int i0 = ig * 9;
    int cs = (c + kk) & 1;
    float* Lx  = buf;                    // [il<9][t<101]: L[cs,(h-i0-il)&63,(t+29)&63]
    float* Ns0 = buf + 912;
    for (int idx = tid; idx < 909; idx += 128) {
        int il = idx / 101; int t = idx - il * 101;
        Lx[idx] = g_L[cs * 4096 + ((h - i0 - il) & 63) * 64 + ((t + 29) & 63)];
    }
    const float* Ntb = g_Nt + (kk * 36 + i0) * NT_SLAB;
    for (int idx = tid; idx < NT_SLAB; idx += 128) Ns0[idx] = Ntb[idx];
    __syncthreads();

    int wq = tid & 7, rg = tid >> 3;
    int w0 = wq * 8, r0 = rg * 4;
    float acc[4][8];
    #pragma unroll
    for (int u = 0; u < 4; u++)
        #pragma unroll
        for (int s = 0; s < 8; s++) acc[u][s] = 0.f;

    for (int il = 0; il < 9; il++) {
        float* cur = Ns0 + (il & 1) * NT_SLAB;
        float* nxt = Ns0 + ((il + 1) & 1) * NT_SLAB;
        if (il < 8) {
            const float* src = Ntb + (il + 1) * NT_SLAB;
            #pragma unroll
            for (int q = 0; q < 19; q++)
                cp_async4(nxt + tid + q * 128, src + tid + q * 128);
            asm volatile("cp.async.commit_group;");
        }
        const float* lrow = Lx + il * 101;
        float W[8];
        #pragma unroll
        for (int s = 0; s < 8; s++) W[s] = lrow[w0 + s + 35];
        #pragma unroll
        for (int j = 0; j < 36; j++) {
            float f0 = cur[(r0 + 0) * 37 + j];
            float f1 = cur[(r0 + 1) * 37 + j];
            float f2 = cur[(r0 + 2) * 37 + j];
            float f3 = cur[(r0 + 3) * 37 + j];
            #pragma unroll
            for (int s = 0; s < 8; s++) {
                acc[0][s] += f0 * W[s];
                acc[1][s] += f1 * W[s];
                acc[2][s] += f2 * W[s];
                acc[3][s] += f3 * W[s];
            }
            if (j < 35) {
                #pragma unroll
                for (int s = 7; s > 0; s--) W[s] = W[s - 1];
                W[0] = lrow[w0 + 34 - j];
            }
        }
        if (il < 8) asm volatile("cp.async.wait_group 0;");
        __syncthreads();
    }
    float* GP = g_GtP + (kk * 4 + ig) * (MK * MDIM);
    int pb = c * 4096 + h * 64 + w0;
    #pragma unroll
    for (int u = 0; u < 4; u++) {
        float4 v0 = make_float4(acc[u][0], acc[u][1], acc[u][2], acc[u][3]);
        float4 v1 = make_float4(acc[u][4], acc[u][5], acc[u][6], acc[u][7]);
        *reinterpret_cast<float4*>(&GP[(r0 + u) * MDIM + pb])     = v0;
        *reinterpret_cast<float4*>(&GP[(r0 + u) * MDIM + pb + 4]) = v1;
    }
}

// ---------------- role: opC  T[r,col] += sum_{c,h,w} L[c,h,w] * Mt[r, adj] (NT=256) -------
__device__ void opc_role(float* buf, int r, int hq, int tid) {
    float* Mtx = buf;             // 2 x 6480 (rows pitch 101)
    float* Lsm = buf + 12960;     // 2 x 16 x 65
    const float* Mrow = g_Mt + r * MDIM;
    for (int idx = tid; idx < 2 * 6464; idx += 256) {
        int cs = idx / 6464; int rem = idx - cs * 6464;
        int hh = rem / 101;  int t = rem - hh * 101;
        Mtx[cs * 6480 + hh * 101 + t] = Mrow[cs * 4096 + hh * 64 + ((t >= 64) ? t - 64 : t)];
    }
    for (int idx = tid; idx < 2048; idx += 256) {
        int cc = idx >> 10; int hl = (idx >> 6) & 15; int w = idx & 63;
        Lsm[(cc * 16 + hl) * 65 + w] = g_L[cc * 4096 + (hq * 16 + hl) * 64 + w];
    }
    __syncthreads();

    int warp = tid >> 5, lane = tid & 31;
    int c = lane >> 4, hl = lane & 15;
    int h = hq * 16 + hl;
    const float* lrow = Lsm + (c * 16 + hl) * 65;

    for (int kp = warp; kp < 72; kp += 8) {
        int k = (kp >= 36) ? 1 : 0;
        int i = kp - k * 36;
        int cs = (c + k) & 1;
        int hs = (h + i) & 63;
        const float* mrow = Mtx + cs * 6480 + hs * 101;

        float acc[36];
        #pragma unroll
        for (int t = 0; t < 36; t++) acc[t] = 0.f;
        float win[35];
        #pragma unroll
        for (int t = 0; t < 35; t++) win[t] = mrow[t];

        #pragma unroll
        for (int w = 0; w < 64; w++) {
            float lv = lrow[w];
            float nv = mrow[w + 35];
            #pragma unroll
            for (int t = 0; t < 35; t++) acc[t] += lv * win[t];
            acc[35] += lv * nv;
            #pragma unroll
            for (int t = 0; t < 34; t++) win[t] = win[t + 1];
            win[34] = nv;
        }

        int colb = r * KC + k * (KK2 * KK1) + i;
        #pragma unroll
        for (int jj = 0; jj < 36; jj++) {
            float s = acc[jj];
            s += __shfl_xor_sync(0xffffffffu, s, 16);
            s += __shfl_xor_sync(0xffffffffu, s, 8);
            s += __shfl_xor_sync(0xffffffffu, s, 4);
            s += __shfl_xor_sync(0xffffffffu, s, 2);
            s += __shfl_xor_sync(0xffffffffu, s, 1);
            if (lane == (jj & 31)) atomicAdd(&g_T[colb + jj * 36], s);
        }
    }
}

// ---------------- CL5/CL6: opC half (128) ∪ {gram1 (64) | inv1 (1)}, 256 threads ---------
__global__ void __launch_bounds__(256) k_cl56(int mode, const float* __restrict__ pa,
                                              const float* __restrict__ pg) {
    __shared__ float buf[15040];
    int tid = threadIdx.x;
    int b = blockIdx.x;
    if (b < 128) {
        opc_role(buf, b & 63, (mode ? 2 : 0) + (b >> 6), tid);
    } else if (mode == 0) {
        gram_role(buf, 1, b - 128, pa, pg, 256, tid);
    } else {
        inv_role(buf, 256, tid);
    }
}

// ---------------- small mm: out = 2*gamma * g_Inv @ X  (+ Nt transpose for which=1) -------
__global__ void __launch_bounds__(256) k_smallmm(int which, const float* __restrict__ pg) {
    __shared__ float As[4096];
    __shared__ float Xs[4096];
    float* out = which ? g_N : g_Mt;
    int Kcols  = which ? KC  : MDIM;
    int tid = threadIdx.x;
    int tx = tid & 63, ty = tid >> 6;
    int cb = blockIdx.x * 64;
    for (int i = tid; i < 4096; i += 256) As[i] = g_Inv[i];
    for (int i = tid; i < 4096; i += 256) {
        int q = i >> 6, cc = cb + (i & 63);
        float v = 0.f;
        if (cc < Kcols) {
            if (which) v = g_T[q * KC + cc];
            else {
                #pragma unroll
                for (int s = 0; s < 8; s++) v += g_GtP[s * (MK * MDIM) + q * MDIM + cc];
            }
        }
        Xs[i] = v;
    }
    __syncthreads();
    float acc[16];
    #pragma unroll
    for (int u = 0; u < 16; u++) acc[u] = 0.f;
    for (int q = 0; q < 64; q++) {
        float xv = Xs[q * 64 + tx];
        #pragma unroll
        for (int u = 0; u < 16; u++)
            acc[u] += As[(ty * 16 + u) * 64 + q] * xv;
    }
    int col = cb + tx;
    if (col < Kcols) {
        float sc = 2.0f * (*pg);
        #pragma unroll
        for (int u = 0; u < 16; u++)
            out[(ty * 16 + u) * Kcols + col] = sc * acc[u];
        if (which) {
            int k2 = col / 1296; int rem = col - k2 * 1296;
            int j  = rem / 36;   int i2 = rem - j * 36;
            float* nt = g_Nt + (k2 * 36 + i2) * NT_SLAB + j;
            #pragma unroll
            for (int u = 0; u < 16; u++)
                nt[(ty * 16 + u) * 37] = sc * acc[u];
        }
    }
}

// =====================================================================================
extern "C" void kernel_launch(void* const* d_in, const int* in_sizes, int n_in,
                              void* d_out, int out_size) {
    const float* img = (const float*)d_in[0];
    const float* S0  = (const float*)d_in[1];
    const float* pa  = (const float*)d_in[2];   // alpha
    const float* pb  = (const float*)d_in[3];   // beta
    const float* pg  = (const float*)d_in[4];   // gamma
    float* out = (float*)d_out;
    (void)in_sizes; (void)n_in; (void)out_size;

    k_init<<<(MK * MDIM + 255) / 256, 256>>>(img, S0);

    for (int it = 0; it < NSTEPS; it++) {
        int last = (it == NSTEPS - 1);
        k_cl1<<<1024, 128>>>();                              // opA, single wave
        k_cl2<<<last ? 32 : 96, 256>>>(img, pa, pg, pb, last, out);  // elem (+gram0)
        if (!last) {
            k_cl3<<<1025, 128>>>();                          // opB + inv0, single wave
            k_smallmm<<<MDIM / 64, 256>>>(0, pg);            // Mt = 2g Inv @ sum(GtP)
            k_cl56<<<192, 256>>>(0, pa, pg);                 // opC(hq0,1) + gram1
            k_cl56<<<129, 256>>>(1, pa, pg);                 // opC(hq2,3) + inv1
            k_smallmm<<<(KC + 63) / 64, 256>>>(1, pg);       // N = 2g Inv @ T (+ Nt)
        }
    }
}

// round 13
// speedup vs baseline: 3.7596x; 1.5365x over previous
#include <cuda_runtime.h>

// Problem constants (B=1, C=2, H=W=64, k1=k2=36, k3=2, iters=6 -> 5 steps)
#define HW    4096
#define MDIM  8192
#define MK    64
#define KC    2592
#define NSTEPS 5
#define RSQ2  0.70710678118654752f

// -------- persistent device state --------
__device__ float  g_L [MDIM];
__device__ float  g_S [MDIM];
__device__ float  g_Mt[MK * MDIM];      // M^T : [r][p]
__device__ float  g_N [MK * KC];        // N   : [r][col]
__device__ float  g_Cm [MK * MK];
__device__ float  g_Inv[MK * MK];
__device__ float2 g_tw  [64];           // W64^t = exp(-2pi i t/64)
__device__ float2 g_Lhat[2 * HW];       // [gamma][hw]  (gamma: 0=+, 1=-)
__device__ float2 g_Mhat[128 * HW];     // [(r*2+gamma)][hw]
__device__ float2 g_Nhat[128 * HW];
__device__ float2 g_What[2 * HW];       // opA freq accumulator
__device__ float  g_Wr [2 * HW];        // opA ifft (unnormalized, per gamma)
__device__ float  g_GB [128 * HW];      // opB ifft planes (unnormalized)
__device__ float  g_TB [128 * HW];      // opC ifft planes (unnormalized)

// -------- complex helpers --------
__device__ __forceinline__ float2 cadd(float2 a, float2 b){ return make_float2(a.x+b.x, a.y+b.y); }
__device__ __forceinline__ float2 csub(float2 a, float2 b){ return make_float2(a.x-b.x, a.y-b.y); }
__device__ __forceinline__ float2 cmul(float2 a, float2 b){ return make_float2(a.x*b.x-a.y*b.y, a.x*b.y+a.y*b.x); }
__device__ __forceinline__ float2 cmulc(float2 a, float2 b){ return make_float2(a.x*b.x+a.y*b.y, a.y*b.x-a.x*b.y); } // a*conj(b)

// 8-point complex DFT, S=+1 fwd (W8 = e^{-2pi i/8}), S=-1 inverse (conj twiddles).
__device__ __forceinline__ void dft8(float2* x, float S){
    float2 t0=cadd(x[0],x[4]), t1=csub(x[0],x[4]);
    float2 t2=cadd(x[2],x[6]), t3=csub(x[2],x[6]);
    float2 E0=cadd(t0,t2), E2=csub(t0,t2);
    float2 j3=make_float2(S*t3.y, -S*t3.x);            // (-S i)*t3
    float2 E1=cadd(t1,j3), E3=csub(t1,j3);
    float2 u0=cadd(x[1],x[5]), u1=csub(x[1],x[5]);
    float2 u2=cadd(x[3],x[7]), u3=csub(x[3],x[7]);
    float2 O0=cadd(u0,u2), O2=csub(u0,u2);
    float2 j4=make_float2(S*u3.y, -S*u3.x);
    float2 O1=cadd(u1,j4), O3=csub(u1,j4);
    float2 W1=make_float2(RSQ2,-S*RSQ2), W3=make_float2(-RSQ2,-S*RSQ2);
    float2 o1=cmul(O1,W1);
    float2 o2=make_float2(S*O2.y,-S*O2.x);             // O2*(0,-S)
    float2 o3=cmul(O3,W3);
    x[0]=cadd(E0,O0); x[4]=csub(E0,O0);
    x[1]=cadd(E1,o1); x[5]=csub(E1,o1);
    x[2]=cadd(E2,o2); x[6]=csub(E2,o2);
    x[3]=cadd(E3,o3); x[7]=csub(E3,o3);
}

// In-place 64x64 complex FFT (rows then cols), 256 threads, A pitch 66 float2/row.
// Unnormalized in both directions (scaling folded into consumers).
// 64-pt = radix-8 two-pass: y[n1][k2]=DFT8_n2(x[n1+8n2]); y'=y*W64^{n1 k2} stored at 8k2+n1;
// X[k2+8k1]=DFT8_n1(y'). Verified on delta/const inputs.
__device__ void fft2d(float2* A, const float2* stw, int tid, float S){
    float2 y[2][8];
    for (int dim = 0; dim < 2; dim++){
        int st = dim ? 66 : 1;
        __syncthreads();
        #pragma unroll
        for (int t2=0;t2<2;t2++){
            int t = tid + t2*256;
            int line = t>>3, n1 = t&7;
            int base = dim ? line : line*66;
            float2 x[8];
            #pragma unroll
            for (int n2=0;n2<8;n2++) x[n2]=A[base+(n1+8*n2)*st];
            dft8(x,S);
            #pragma unroll
            for (int k2=0;k2<8;k2++){
                float2 w = stw[n1*k2];
                if (S < 0.f) w.y = -w.y;
                y[t2][k2]=cmul(x[k2],w);
            }
        }
        __syncthreads();
        #pragma unroll
        for (int t2=0;t2<2;t2++){
            int t=tid+t2*256; int line=t>>3, n1=t&7;
            int base = dim ? line : line*66;
            #pragma unroll
            for (int k2=0;k2<8;k2++) A[base+(8*k2+n1)*st]=y[t2][k2];
        }
        __syncthreads();
        #pragma unroll
        for (int t2=0;t2<2;t2++){
            int t=tid+t2*256; int line=t>>3, k2=t&7;
            int base = dim ? line : line*66;
            float2 x[8];
            #pragma unroll
            for (int n1=0;n1<8;n1++) x[n1]=A[base+(8*k2+n1)*st];
            dft8(x,S);
            #pragma unroll
            for (int k1=0;k1<8;k1++) y[t2][k1]=x[k1];
        }
        __syncthreads();
        #pragma unroll
        for (int t2=0;t2<2;t2++){
            int t=tid+t2*256; int line=t>>3, k2=t&7;
            int base = dim ? line : line*66;
            #pragma unroll
            for (int k1=0;k1<8;k1++) A[base+(k2+8*k1)*st]=y[t2][k1];
        }
    }
    __syncthreads();
}

// ---------------- init: L=img, S=S0, Mt=eye, N=eye, twiddles ----------------
__global__ void k_init(const float* __restrict__ img, const float* __restrict__ S0) {
    int idx = blockIdx.x * 256 + threadIdx.x;
    if (idx < MDIM) { g_L[idx] = img[idx]; g_S[idx] = S0[idx]; }
    if (idx < MK * MDIM) {
        int r = idx >> 13, p = idx & (MDIM - 1);
        g_Mt[idx] = (p == r) ? 1.0f : 0.0f;
    }
    if (idx < MK * KC) {
        int r = idx / KC, c = idx - r * KC;
        g_N[idx] = (c == r) ? 1.0f : 0.0f;
    }
    if (idx < 64) {
        float a = 6.2831853071795864f * (float)idx / 64.0f;
        g_tw[idx] = make_float2(cosf(a), -sinf(a));
    }
}

// ---------------- role: gram  g_Cm = alpha*I + 2*gamma * X X^T ----------------
__device__ void gram_role(float* buf, int which, int a,
                          const float* pa, const float* pg, int NT, int tid) {
    const float* X = which ? g_Mt : g_N;
    int K = which ? MDIM : KC;
    for (int i = tid; i < K; i += NT) buf[i] = X[a * K + i];
    __syncthreads();
    int warp = tid >> 5, lane = tid & 31, nw = NT >> 5;
    for (int b = warp; b < MK; b += nw) {
        const float* xb = X + b * K;
        float s = 0.f;
        for (int kk = lane; kk < K; kk += 32) s += buf[kk] * xb[kk];
        #pragma unroll
        for (int o = 16; o; o >>= 1) s += __shfl_xor_sync(0xffffffffu, s, o);
        if (lane == 0) {
            float v = 2.0f * (*pg) * s;
            if (a == b) v += *pa;
            g_Cm[a * MK + b] = v;
        }
    }
}

// ---------------- role: 64x64 SPD inverse, in-place Gauss-Jordan ----------------
__device__ void inv_role(float* buf, int NT, int tid) {
    float* a    = buf;            // 64 x 65
    float* colk = buf + 4160;
    for (int idx = tid; idx < 64 * 64; idx += NT)
        a[(idx >> 6) * 65 + (idx & 63)] = g_Cm[idx];
    __syncthreads();
    for (int k = 0; k < 64; k++) {
        float p = 1.0f / a[k * 65 + k];
        for (int i = tid; i < 64; i += NT) colk[i] = a[i * 65 + k];
        __syncthreads();
        for (int j = tid; j < 64; j += NT)
            a[k * 65 + j] = (j == k) ? p : a[k * 65 + j] * p;
        __syncthreads();
        for (int idx = tid; idx < 64 * 64; idx += NT) {
            int i = idx >> 6, j = idx & 63;
            if (i != k)
                a[i * 65 + j] = (j == k) ? -colk[i] * p
                                         : a[i * 65 + j] - colk[i] * a[k * 65 + j];
        }
        __syncthreads();
    }
    for (int idx = tid; idx < 64 * 64; idx += NT)
        g_Inv[idx] = a[(idx >> 6) * 65 + (idx & 63)];
}

// ---------------- the FFT mega-kernel ----------------
// mode 0: FWD L   (grid 2:  b=gamma)        L -> g_Lhat
// mode 1: FWD Mt  (grid 128(+64 gram1): b=r*2+gamma)  g_Mt -> g_Mhat
// mode 2: FWD N   (grid 128) padded N'(r) -> g_Nhat   [N'[k][h=i][w=j]=N[r,(k*36+j)*36+i]]
// mode 3: IFFT A  (grid 2)  g_What -> g_Wr (re)
// mode 4: OPB     (grid 128(+1 inv)): ifft(Nhat*Lhat) -> g_GB (re)
// mode 5: OPC     (grid 128(+1 inv)): ifft(Mhat*conj(Lhat)) -> g_TB (re)
__global__ __launch_bounds__(256) void k_fft(int mode, const float* __restrict__ pa,
                                             const float* __restrict__ pg) {
    __shared__ float2 sb[4288];          // A: 64x66 = 4224 | stw: 64
    int tid = threadIdx.x, b = blockIdx.x;
    if (mode == 1 && b >= 128) { gram_role((float*)sb, 1, b - 128, pa, pg, 256, tid); return; }
    if (mode >= 4 && b >= 128) { inv_role((float*)sb, 256, tid); return; }

    float2* A   = sb;
    float2* stw = sb + 4224;
    if (tid < 64) stw[tid] = g_tw[tid];

    int gamma = (mode == 0 || mode == 3) ? b : (b & 1);
    int r = b >> 1;
    float s = gamma ? -1.f : 1.f;

    if (mode == 0) {
        for (int i = tid; i < 4096; i += 256)
            A[(i >> 6) * 66 + (i & 63)] = make_float2(g_L[i] + s * g_L[HW + i], 0.f);
    } else if (mode == 1) {
        const float* M = g_Mt + r * MDIM;
        for (int i = tid; i < 4096; i += 256)
            A[(i >> 6) * 66 + (i & 63)] = make_float2(M[i] + s * M[HW + i], 0.f);
    } else if (mode == 2) {
        const float* Nr = g_N + r * KC;
        for (int i = tid; i < 4096; i += 256) {
            int h = i >> 6, w = i & 63;
            float v = 0.f;
            if (h < 36 && w < 36) v = Nr[w * 36 + h] + s * Nr[(36 + w) * 36 + h];
            A[h * 66 + w] = make_float2(v, 0.f);
        }
    } else if (mode == 3) {
        const float2* Wv = g_What + gamma * HW;
        for (int i = tid; i < 4096; i += 256)
            A[(i >> 6) * 66 + (i & 63)] = Wv[i];
    } else if (mode == 4) {
        const float2* Nh = g_Nhat + b * HW;
        const float2* Lh = g_Lhat + gamma * HW;
        for (int i = tid; i < 4096; i += 256)
            A[(i >> 6) * 66 + (i & 63)] = cmul(Nh[i], Lh[i]);
    } else {
        const float2* Mh = g_Mhat + b * HW;
        const float2* Lh = g_Lhat + gamma * HW;
        for (int i = tid; i < 4096; i += 256)
            A[(i >> 6) * 66 + (i & 63)] = cmulc(Mh[i], Lh[i]);
    }

    float S = (mode >= 3) ? -1.f : 1.f;
    fft2d(A, stw, tid, S);

    if (mode == 0) {
        float2* d = g_Lhat + gamma * HW;
        for (int i = tid; i < 4096; i += 256) d[i] = A[(i >> 6) * 66 + (i & 63)];
    } else if (mode == 1) {
        float2* d = g_Mhat + b * HW;
        for (int i = tid; i < 4096; i += 256) d[i] = A[(i >> 6) * 66 + (i & 63)];
    } else if (mode == 2) {
        float2* d = g_Nhat + b * HW;
        for (int i = tid; i < 4096; i += 256) d[i] = A[(i >> 6) * 66 + (i & 63)];
    } else if (mode == 3) {
        for (int i = tid; i < 4096; i += 256) g_Wr[gamma * HW + i] = A[(i >> 6) * 66 + (i & 63)].x;
    } else if (mode == 4) {
        for (int i = tid; i < 4096; i += 256) g_GB[b * HW + i] = A[(i >> 6) * 66 + (i & 63)].x;
    } else {
        for (int i = tid; i < 4096; i += 256) g_TB[b * HW + i] = A[(i >> 6) * 66 + (i & 63)].x;
    }
}

// ---------------- opA frequency accumulation: What = sum_r Mhat_r * conj(Nhat_r) ----------
__global__ __launch_bounds__(256) void k_opAsum() {
    int gw = blockIdx.x * 256 + threadIdx.x;      // 0..8191  (gamma*4096 + w)
    int gamma = gw >> 12, w = gw & 4095;
    const float2* M = g_Mhat + gamma * HW + w;
    const float2* N = g_Nhat + gamma * HW + w;
    float2 acc = make_float2(0.f, 0.f);
    #pragma unroll 8
    for (int r = 0; r < 64; r++) {
        float2 a = M[r * 2 * HW], bb = N[r * 2 * HW];
        acc.x += a.x * bb.x + a.y * bb.y;
        acc.y += a.y * bb.x - a.x * bb.y;
    }
    g_What[gw] = acc;
}

// ---------------- CL2: elementwise L/S update (reads Wr) ∪ gram0, 256 threads ----------
__global__ void __launch_bounds__(256) k_cl2(const float* __restrict__ img,
                                             const float* __restrict__ pa,
                                             const float* __restrict__ pg,
                                             const float* __restrict__ pb,
                                             int final, float* __restrict__ out) {
    __shared__ float buf[2592];
    int tid = threadIdx.x;
    int b = blockIdx.x;
    if (b >= 32) { gram_role(buf, 0, b - 32, pa, pg, 256, tid); return; }

    int p = b * 256 + tid;               // p < 8192
    int p2 = p & 4095;
    float sg = (p >> 12) ? -1.f : 1.f;
    float gam = *pg, bet = *pb;
    float akadj = (g_Wr[p2] + sg * g_Wr[HW + p2]) * (1.0f / (8192.0f * 2592.0f));
    float ln = (img[p] - g_S[p] + gam * akadj) / (gam + 1.0f);
    ln = fminf(fmaxf(ln, 0.0f), 1.0f);
    g_L[p] = ln;
    g_S[p] = (img[p] - ln) / (bet + 1.0f);
    if (final) out[p] = ln;
}

// ---------------- small mm: out = 2*gamma * g_Inv @ X ----------------
// which=0: X = Gt from GB planes (combine +-, /8192), out=g_Mt, Kcols=8192
// which=1: X = T  from TB planes (gather 36x36x2 corner), out=g_N, Kcols=2592
__global__ void __launch_bounds__(256) k_smallmm(int which, const float* __restrict__ pg) {
    __shared__ float As[4096];
    __shared__ float Xs[4096];
    float* out = which ? g_N : g_Mt;
    int Kcols  = which ? KC  : MDIM;
    int tid = threadIdx.x;
    int tx = tid & 63, ty = tid >> 6;
    int cb = blockIdx.x * 64;
    const float SCL = 1.0f / 8192.0f;
    for (int i = tid; i < 4096; i += 256) As[i] = g_Inv[i];
    for (int i = tid; i < 4096; i += 256) {
        int q = i >> 6, cc = cb + (i & 63);
        float v = 0.f;
        if (cc < Kcols) {
            if (which) {
                int k2 = cc / 1296; int rem = cc - k2 * 1296;
                int j  = rem / 36;  int ii = rem - j * 36;
                int p2 = ii * 64 + j;
                float sgk = k2 ? -1.f : 1.f;
                v = (g_TB[(q * 2) * HW + p2] + sgk * g_TB[(q * 2 + 1) * HW + p2]) * SCL;
            } else {
                int c = cc >> 12; int p2 = cc & 4095;
                float sgc = c ? -1.f : 1.f;
                v = (g_GB[(q * 2) * HW + p2] + sgc * g_GB[(q * 2 + 1) * HW + p2]) * SCL;
            }
        }
        Xs[i] = v;
    }
    __syncthreads();
    float acc[16];
    #pragma unroll
    for (int u = 0; u < 16; u++) acc[u] = 0.f;
    for (int q = 0; q < 64; q++) {
        float xv = Xs[q * 64 + tx];
        #pragma unroll
        for (int u = 0; u < 16; u++)
            acc[u] += As[(ty * 16 + u) * 64 + q] * xv;
    }
    int col = cb + tx;
    if (col < Kcols) {
        float sc = 2.0f * (*pg);
        #pragma unroll
        for (int u = 0; u < 16; u++)
            out[(ty * 16 + u) * Kcols + col] = sc * acc[u];
    }
}

// =====================================================================================
extern "C" void kernel_launch(void* const* d_in, const int* in_sizes, int n_in,
                              void* d_out, int out_size) {
    const float* img = (const float*)d_in[0];
    const float* S0  = (const float*)d_in[1];
    const float* pa  = (const float*)d_in[2];   // alpha
    const float* pb  = (const float*)d_in[3];   // beta
    const float* pg  = (const float*)d_in[4];   // gamma
    float* out = (float*)d_out;
    (void)in_sizes; (void)n_in; (void)out_size;

    k_init<<<(MK * MDIM + 255) / 256, 256>>>(img, S0);
    k_fft<<<128, 256>>>(1, pa, pg);              // Mhat(eye)
    k_fft<<<128, 256>>>(2, pa, pg);              // Nhat(eye)

    for (int it = 0; it < NSTEPS; it++) {
        int last = (it == NSTEPS - 1);
        k_opAsum<<<32, 256>>>();                 // What = sum_r Mhat conj(Nhat)
        k_fft<<<2, 256>>>(3, pa, pg);            // Wr = ifft(What)
        k_cl2<<<last ? 32 : 96, 256>>>(img, pa, pg, pb, last, out);   // elem (+gram0)
        if (!last) {
            k_fft<<<2, 256>>>(0, pa, pg);        // Lhat
            k_fft<<<129, 256>>>(4, pa, pg);      // GB = ifft(Nhat*Lhat)  (+inv0)
            k_smallmm<<<MDIM / 64, 256>>>(0, pg);   // Mt = 2g Inv @ Gt
            k_fft<<<192, 256>>>(1, pa, pg);      // Mhat (+gram1)
            k_fft<<<129, 256>>>(5, pa, pg);      // TB = ifft(Mhat*conj(Lhat)) (+inv1)
            k_smallmm<<<(KC + 63) / 64, 256>>>(1, pg);  // N = 2g Inv @ T
            k_fft<<<128, 256>>>(2, pa, pg);      // Nhat
        }
    }
}

// round 15
// speedup vs baseline: 5.1201x; 1.3619x over previous
#include <cuda_runtime.h>

// Problem constants (B=1, C=2, H=W=64, k1=k2=36, k3=2, iters=6 -> 5 steps)
#define HW    4096
#define MDIM  8192
#define MK    64
#define KC    2592
#define NSTEPS 5
#define RSQ2  0.70710678118654752f
#define AKSCL (1.0f / (8192.0f * 2592.0f))

// -------- persistent device state --------
__device__ float  g_Sb[2][MDIM];        // S ping-pong
__device__ float  g_Mt[MK * MDIM];      // M^T : [r][p]
__device__ float  g_N [MK * KC];        // N   : [r][col]
__device__ float  g_Cm [MK * MK];
__device__ float  g_Inv[MK * MK];
__device__ float2 g_tw  [64];           // W64^t = exp(-2pi i t/64)
__device__ float2 g_Lhat[2 * HW];       // [gamma][hw]
__device__ float2 g_Mhat[128 * HW];     // [(r*2+gamma)][hw]
__device__ float2 g_Nhat[128 * HW];
__device__ float2 g_WhatP[8 * 2 * HW];  // opA partial sums: [rg][gamma*HW+pt]
__device__ float  g_Wr [2 * HW];        // opA ifft (unnormalized, per gamma)
__device__ float  g_GB [128 * HW];      // opB ifft planes (unnormalized)
__device__ float  g_TB [128 * HW];      // opC ifft planes (unnormalized)

// -------- complex helpers --------
__device__ __forceinline__ float2 cadd(float2 a, float2 b){ return make_float2(a.x+b.x, a.y+b.y); }
__device__ __forceinline__ float2 csub(float2 a, float2 b){ return make_float2(a.x-b.x, a.y-b.y); }
__device__ __forceinline__ float2 cmul(float2 a, float2 b){ return make_float2(a.x*b.x-a.y*b.y, a.x*b.y+a.y*b.x); }
__device__ __forceinline__ float2 cmulc(float2 a, float2 b){ return make_float2(a.x*b.x+a.y*b.y, a.y*b.x-a.x*b.y); } // a*conj(b)

// 8-point complex DFT, S=+1 fwd (W8 = e^{-2pi i/8}), S=-1 inverse (conj twiddles).
__device__ __forceinline__ void dft8(float2* x, float S){
    float2 t0=cadd(x[0],x[4]), t1=csub(x[0],x[4]);
    float2 t2=cadd(x[2],x[6]), t3=csub(x[2],x[6]);
    float2 E0=cadd(t0,t2), E2=csub(t0,t2);
    float2 j3=make_float2(S*t3.y, -S*t3.x);
    float2 E1=cadd(t1,j3), E3=csub(t1,j3);
    float2 u0=cadd(x[1],x[5]), u1=csub(x[1],x[5]);
    float2 u2=cadd(x[3],x[7]), u3=csub(x[3],x[7]);
    float2 O0=cadd(u0,u2), O2=csub(u0,u2);
    float2 j4=make_float2(S*u3.y, -S*u3.x);
    float2 O1=cadd(u1,j4), O3=csub(u1,j4);
    float2 W1=make_float2(RSQ2,-S*RSQ2), W3=make_float2(-RSQ2,-S*RSQ2);
    float2 o1=cmul(O1,W1);
    float2 o2=make_float2(S*O2.y,-S*O2.x);
    float2 o3=cmul(O3,W3);
    x[0]=cadd(E0,O0); x[4]=csub(E0,O0);
    x[1]=cadd(E1,o1); x[5]=csub(E1,o1);
    x[2]=cadd(E2,o2); x[6]=csub(E2,o2);
    x[3]=cadd(E3,o3); x[7]=csub(E3,o3);
}

// In-place 64x64 complex FFT, 512 threads (one (line, n1) pair per thread).
// A pitch 66 float2/row. Unnormalized both directions.
__device__ void fft2d(float2* A, const float2* stw, int tid, float S){
    int line = tid >> 3, n1 = tid & 7;
    #pragma unroll
    for (int dim = 0; dim < 2; dim++){
        int st   = dim ? 66 : 1;
        int base = dim ? line : line * 66;
        __syncthreads();
        float2 x[8];
        #pragma unroll
        for (int n2=0;n2<8;n2++) x[n2]=A[base+(n1+8*n2)*st];
        dft8(x,S);
        float2 y[8];
        #pragma unroll
        for (int k2=0;k2<8;k2++){
            float2 w = stw[n1*k2];
            if (S < 0.f) w.y = -w.y;
            y[k2]=cmul(x[k2],w);
        }
        __syncthreads();
        #pragma unroll
        for (int k2=0;k2<8;k2++) A[base+(8*k2+n1)*st]=y[k2];
        __syncthreads();
        // second pass: this thread takes k2 = n1
        #pragma unroll
        for (int q=0;q<8;q++) x[q]=A[base+(8*n1+q)*st];
        dft8(x,S);
        __syncthreads();
        #pragma unroll
        for (int k1=0;k1<8;k1++) A[base+(n1+8*k1)*st]=x[k1];
    }
    __syncthreads();
}

// ---------------- init: S=S0, Mt=eye, N=eye, twiddles ----------------
__global__ void k_init(const float* __restrict__ img, const float* __restrict__ S0) {
    int idx = blockIdx.x * 256 + threadIdx.x;
    (void)img;
    if (idx < MDIM) g_Sb[0][idx] = S0[idx];
    if (idx < MK * MDIM) {
        int r = idx >> 13, p = idx & (MDIM - 1);
        g_Mt[idx] = (p == r) ? 1.0f : 0.0f;
    }
    if (idx < MK * KC) {
        int r = idx / KC, c = idx - r * KC;
        g_N[idx] = (c == r) ? 1.0f : 0.0f;
    }
    if (idx < 64) {
        float a = 6.2831853071795864f * (float)idx / 64.0f;
        g_tw[idx] = make_float2(cosf(a), -sinf(a));
    }
}

// ---------------- role: gram  g_Cm = alpha*I + 2*gamma * X X^T ----------------
__device__ void gram_role(float* buf, int which, int a,
                          const float* pa, const float* pg, int NT, int tid) {
    const float* X = which ? g_Mt : g_N;
    int K = which ? MDIM : KC;
    for (int i = tid; i < K; i += NT) buf[i] = X[a * K + i];
    __syncthreads();
    int warp = tid >> 5, lane = tid & 31, nw = NT >> 5;
    for (int b = warp; b < MK; b += nw) {
        const float* xb = X + b * K;
        float s = 0.f;
        for (int kk = lane; kk < K; kk += 32) s += buf[kk] * xb[kk];
        #pragma unroll
        for (int o = 16; o; o >>= 1) s += __shfl_xor_sync(0xffffffffu, s, o);
        if (lane == 0) {
            float v = 2.0f * (*pg) * s;
            if (a == b) v += *pa;
            g_Cm[a * MK + b] = v;
        }
    }
}

// ---------------- role: 64x64 SPD inverse, in-place Gauss-Jordan ----------------
__device__ void inv_role(float* buf, int NT, int tid) {
    float* a    = buf;            // 64 x 65
    float* colk = buf + 4160;
    for (int idx = tid; idx < 64 * 64; idx += NT)
        a[(idx >> 6) * 65 + (idx & 63)] = g_Cm[idx];
    __syncthreads();
    for (int k = 0; k < 64; k++) {
        float p = 1.0f / a[k * 65 + k];
        for (int i = tid; i < 64; i += NT) colk[i] = a[i * 65 + k];
        __syncthreads();
        for (int j = tid; j < 64; j += NT)
            a[k * 65 + j] = (j == k) ? p : a[k * 65 + j] * p;
        __syncthreads();
        for (int idx = tid; idx < 64 * 64; idx += NT) {
            int i = idx >> 6, j = idx & 63;
            if (i != k)
                a[i * 65 + j] = (j == k) ? -colk[i] * p
                                         : a[i * 65 + j] - colk[i] * a[k * 65 + j];
        }
        __syncthreads();
    }
    for (int idx = tid; idx < 64 * 64; idx += NT)
        g_Inv[idx] = a[(idx >> 6) * 65 + (idx & 63)];
}

// ---------------- FFT mega-kernel (512 threads) ----------------
// mode 1: FWD Mt  (grid 128 (+64 gram1)): g_Mt -> g_Mhat
// mode 2: FWD N   (grid 128): padded N'(r) -> g_Nhat
// mode 3: IFFT A  (grid 2 (+64 gram0)): sum(WhatP) -> g_Wr (re)
// mode 4: OPB     (grid 128 (+1 inv0)): ifft(Nhat*Lhat) -> g_GB (re)
// mode 5: OPC     (grid 128 (+1 inv1)): ifft(Mhat*conj(Lhat)) -> g_TB (re)
__global__ __launch_bounds__(512) void k_fft(int mode, const float* __restrict__ pa,
                                             const float* __restrict__ pg) {
    __shared__ float2 sb[4288];          // A: 64x66 = 4224 | stw: 64
    int tid = threadIdx.x, b = blockIdx.x;
    if (mode == 1 && b >= 128) { gram_role((float*)sb, 1, b - 128, pa, pg, 512, tid); return; }
    if (mode == 3 && b >= 2)   { gram_role((float*)sb, 0, b - 2,   pa, pg, 512, tid); return; }
    if (mode >= 4 && b >= 128) { inv_role((float*)sb, 512, tid); return; }

    float2* A   = sb;
    float2* stw = sb + 4224;
    if (tid < 64) stw[tid] = g_tw[tid];

    int gamma = (mode == 3) ? b : (b & 1);
    int r = b >> 1;
    float s = gamma ? -1.f : 1.f;

    if (mode == 1) {
        const float* M = g_Mt + r * MDIM;
        for (int i = tid; i < 4096; i += 512)
            A[(i >> 6) * 66 + (i & 63)] = make_float2(M[i] + s * M[HW + i], 0.f);
    } else if (mode == 2) {
        const float* Nr = g_N + r * KC;
        for (int i = tid; i < 4096; i += 512) {
            int h = i >> 6, w = i & 63;
            float v = 0.f;
            if (h < 36 && w < 36) v = Nr[w * 36 + h] + s * Nr[(36 + w) * 36 + h];
            A[h * 66 + w] = make_float2(v, 0.f);
        }
    } else if (mode == 3) {
        for (int i = tid; i < 4096; i += 512) {
            float2 acc = make_float2(0.f, 0.f);
            #pragma unroll
            for (int sgrp = 0; sgrp < 8; sgrp++)
                acc = cadd(acc, g_WhatP[sgrp * 2 * HW + gamma * HW + i]);
            A[(i >> 6) * 66 + (i & 63)] = acc;
        }
    } else if (mode == 4) {
        const float2* Nh = g_Nhat + b * HW;
        const float2* Lh = g_Lhat + gamma * HW;
        for (int i = tid; i < 4096; i += 512)
            A[(i >> 6) * 66 + (i & 63)] = cmul(Nh[i], Lh[i]);
    } else {
        const float2* Mh = g_Mhat + b * HW;
        const float2* Lh = g_Lhat + gamma * HW;
        for (int i = tid; i < 4096; i += 512)
            A[(i >> 6) * 66 + (i & 63)] = cmulc(Mh[i], Lh[i]);
    }

    float S = (mode >= 3) ? -1.f : 1.f;
    fft2d(A, stw, tid, S);

    if (mode == 1) {
        float2* d = g_Mhat + b * HW;
        for (int i = tid; i < 4096; i += 512) d[i] = A[(i >> 6) * 66 + (i & 63)];
    } else if (mode == 2) {
        float2* d = g_Nhat + b * HW;
        for (int i = tid; i < 4096; i += 512) d[i] = A[(i >> 6) * 66 + (i & 63)];
    } else if (mode == 3) {
        for (int i = tid; i < 4096; i += 512) g_Wr[gamma * HW + i] = A[(i >> 6) * 66 + (i & 63)].x;
    } else if (mode == 4) {
        for (int i = tid; i < 4096; i += 512) g_GB[b * HW + i] = A[(i >> 6) * 66 + (i & 63)].x;
    } else {
        for (int i = tid; i < 4096; i += 512) g_TB[b * HW + i] = A[(i >> 6) * 66 + (i & 63)].x;
    }
}

// ---------------- opA partial sums: WhatP[rg] = sum_{r in rg} Mhat_r * conj(Nhat_r) -------
__global__ __launch_bounds__(256) void k_opAsum() {
    int b = blockIdx.x;                       // 256 blocks
    int rg = b & 7, chunk = b >> 3;           // 8 r-groups x 32 point-chunks
    int gw = chunk * 256 + threadIdx.x;       // 0..8191
    int gamma = gw >> 12, pt = gw & 4095;
    float2 acc = make_float2(0.f, 0.f);
    #pragma unroll
    for (int rr = 0; rr < 8; rr++) {
        int r = rg * 8 + rr;
        float2 a  = g_Mhat[(r * 2 + gamma) * HW + pt];
        float2 bb = g_Nhat[(r * 2 + gamma) * HW + pt];
        acc.x += a.x * bb.x + a.y * bb.y;
        acc.y += a.y * bb.x - a.x * bb.y;
    }
    g_WhatP[rg * 2 * HW + gw] = acc;
}

// ---------------- k_lelem: elem update (both blocks) + forward L-FFT (per gamma) ----------
// grid 2 (or 1 when final). Block 0 persists S (ping-pong) and out.
__global__ __launch_bounds__(512) void k_lelem(const float* __restrict__ img,
                                               const float* __restrict__ pg,
                                               const float* __restrict__ pb,
                                               int par, int final, float* __restrict__ out) {
    __shared__ float2 sb[4288];
    int tid = threadIdx.x, b = blockIdx.x;
    float2* A   = sb;
    float2* stw = sb + 4224;
    if (tid < 64) stw[tid] = g_tw[tid];
    float gam = *pg, bet = *pb;
    const float* Sc = g_Sb[par];
    float*       Sn = g_Sb[par ^ 1];
    float sg = b ? -1.f : 1.f;

    for (int i = tid; i < 4096; i += 512) {
        float w0 = g_Wr[i], w1 = g_Wr[HW + i];
        float ak0 = (w0 + w1) * AKSCL;
        float ak1 = (w0 - w1) * AKSCL;
        float i0 = img[i], i1 = img[HW + i];
        float l0 = fminf(fmaxf((i0 - Sc[i]      + gam * ak0) / (gam + 1.f), 0.f), 1.f);
        float l1 = fminf(fmaxf((i1 - Sc[HW + i] + gam * ak1) / (gam + 1.f), 0.f), 1.f);
        if (b == 0) {
            Sn[i]      = (i0 - l0) / (bet + 1.f);
            Sn[HW + i] = (i1 - l1) / (bet + 1.f);
            if (final) { out[i] = l0; out[HW + i] = l1; }
        }
        A[(i >> 6) * 66 + (i & 63)] = make_float2(l0 + sg * l1, 0.f);
    }
    if (final) return;
    fft2d(A, stw, tid, 1.f);
    float2* d = g_Lhat + b * HW;
    for (int i = tid; i < 4096; i += 512) d[i] = A[(i >> 6) * 66 + (i & 63)];
}

// ---------------- small mm: out = 2*gamma * g_Inv @ X ----------------
__global__ void __launch_bounds__(256) k_smallmm(int which, const float* __restrict__ pg) {
    __shared__ float As[4096];
    __shared__ float Xs[4096];
    float* out = which ? g_N : g_Mt;
    int Kcols  = which ? KC  : MDIM;
    int tid = threadIdx.x;
    int tx = tid & 63, ty = tid >> 6;
    int cb = blockIdx.x * 64;
    const float SCL = 1.0f / 8192.0f;
    for (int i = tid; i < 4096; i += 256) As[i] = g_Inv[i];
    for (int i = tid; i < 4096; i += 256) {
        int q = i >> 6, cc = cb + (i & 63);
        float v = 0.f;
        if (cc < Kcols) {
            if (which) {
                int k2 = cc / 1296; int rem = cc - k2 * 1296;
                int j  = rem / 36;  int ii = rem - j * 36;
                int p2 = ii * 64 + j;
                float sgk = k2 ? -1.f : 1.f;
                v = (g_TB[(q * 2) * HW + p2] + sgk * g_TB[(q * 2 + 1) * HW + p2]) * SCL;
            } else {
                int c = cc >> 12; int p2 = cc & 4095;
                float sgc = c ? -1.f : 1.f;
                v = (g_GB[(q * 2) * HW + p2] + sgc * g_GB[(q * 2 + 1) * HW + p2]) * SCL;
            }
        }
        Xs[i] = v;
    }
    __syncthreads();
    float acc[16];
    #pragma unroll
    for (int u = 0; u < 16; u++) acc[u] = 0.f;
    for (int q = 0; q < 64; q++) {
        float xv = Xs[q * 64 + tx];
        #pragma unroll
        for (int u = 0; u < 16; u++)
            acc[u] += As[(ty * 16 + u) * 64 + q] * xv;
    }
    int col = cb + tx;
    if (col < Kcols) {
        float sc = 2.0f * (*pg);
        #pragma unroll
        for (int u = 0; u < 16; u++)
            out[(ty * 16 + u) * Kcols + col] = sc * acc[u];
    }
}

// =====================================================================================
extern "C" void kernel_launch(void* const* d_in, const int* in_sizes, int n_in,
                              void* d_out, int out_size) {
    const float* img = (const float*)d_in[0];
    const float* S0  = (const float*)d_in[1];
    const float* pa  = (const float*)d_in[2];   // alpha
    const float* pb  = (const float*)d_in[3];   // beta
    const float* pg  = (const float*)d_in[4];   // gamma
    float* out = (float*)d_out;
    (void)in_sizes; (void)n_in; (void)out_size;

    k_init<<<(MK * MDIM + 255) / 256, 256>>>(img, S0);
    k_fft<<<128, 512>>>(1, pa, pg);              // Mhat(eye)
    k_fft<<<128, 512>>>(2, pa, pg);              // Nhat(eye)

    for (int it = 0; it < NSTEPS; it++) {
        int last = (it == NSTEPS - 1);
        k_opAsum<<<256, 256>>>();                               // WhatP partials
        k_fft<<<last ? 2 : 66, 512>>>(3, pa, pg);               // Wr = ifft(sum WhatP) (+gram0)
        k_lelem<<<last ? 1 : 2, 512>>>(img, pg, pb, it & 1, last, out);  // elem (+Lhat fft)
        if (!last) {
            k_fft<<<129, 512>>>(4, pa, pg);                     // GB = ifft(Nhat*Lhat) (+inv0)
            k_smallmm<<<MDIM / 64, 256>>>(0, pg);               // Mt = 2g Inv @ Gt
            k_fft<<<192, 512>>>(1, pa, pg);                     // Mhat (+gram1)
            k_fft<<<129, 512>>>(5, pa, pg);                     // TB = ifft(Mhat*conj(Lhat)) (+inv1)
            k_smallmm<<<(KC + 63) / 64, 256>>>(1, pg);          // N = 2g Inv @ T
            k_fft<<<128, 512>>>(2, pa, pg);                     // Nhat
        }
    }
}

// round 17
// speedup vs baseline: 5.6037x; 1.0944x over previous
#include <cuda_runtime.h>

// Problem constants (B=1, C=2, H=W=64, k1=k2=36, k3=2, iters=6 -> 5 steps)
#define HW    4096
#define MDIM  8192
#define MK    64
#define KC    2592
#define NSTEPS 5
#define RSQ2  0.70710678118654752f
#define AKSCL (1.0f / (8192.0f * 2592.0f))

// -------- persistent device state --------
__device__ float  g_Sb[2][MDIM];        // S ping-pong
__device__ float  g_N [MK * KC];        // N spatial : [r][col]
__device__ float  g_Cm [MK * MK];
__device__ float  g_Inv[MK * MK];
__device__ float2 g_tw  [64];           // W64^t = exp(-2pi i t/64)
__device__ float2 g_Lhat[2 * HW];       // [gamma][hw]
__device__ float2 g_Mhat[128 * HW];     // [(r*2+gamma)][hw]  (M lives ONLY here)
__device__ float2 g_Nhat[128 * HW];
__device__ float2 g_WhatP[8 * 2 * HW];  // opA partial sums
__device__ float  g_Wr [2 * HW];        // opA ifft (unnormalized)
__device__ float  g_TB [128 * HW];      // opC ifft planes (unnormalized)

// -------- complex helpers --------
__device__ __forceinline__ float2 cadd(float2 a, float2 b){ return make_float2(a.x+b.x, a.y+b.y); }
__device__ __forceinline__ float2 csub(float2 a, float2 b){ return make_float2(a.x-b.x, a.y-b.y); }
__device__ __forceinline__ float2 cmul(float2 a, float2 b){ return make_float2(a.x*b.x-a.y*b.y, a.x*b.y+a.y*b.x); }
__device__ __forceinline__ float2 cmulc(float2 a, float2 b){ return make_float2(a.x*b.x+a.y*b.y, a.y*b.x-a.x*b.y); } // a*conj(b)
__device__ __forceinline__ float2 twf(int t){
    float a = 6.2831853071795864f * (float)t * (1.0f / 64.0f);
    return make_float2(cosf(a), -sinf(a));
}

// 8-point complex DFT, S=+1 fwd, S=-1 inverse.
__device__ __forceinline__ void dft8(float2* x, float S){
    float2 t0=cadd(x[0],x[4]), t1=csub(x[0],x[4]);
    float2 t2=cadd(x[2],x[6]), t3=csub(x[2],x[6]);
    float2 E0=cadd(t0,t2), E2=csub(t0,t2);
    float2 j3=make_float2(S*t3.y, -S*t3.x);
    float2 E1=cadd(t1,j3), E3=csub(t1,j3);
    float2 u0=cadd(x[1],x[5]), u1=csub(x[1],x[5]);
    float2 u2=cadd(x[3],x[7]), u3=csub(x[3],x[7]);
    float2 O0=cadd(u0,u2), O2=csub(u0,u2);
    float2 j4=make_float2(S*u3.y, -S*u3.x);
    float2 O1=cadd(u1,j4), O3=csub(u1,j4);
    float2 W1=make_float2(RSQ2,-S*RSQ2), W3=make_float2(-RSQ2,-S*RSQ2);
    float2 o1=cmul(O1,W1);
    float2 o2=make_float2(S*O2.y,-S*O2.x);
    float2 o3=cmul(O3,W3);
    x[0]=cadd(E0,O0); x[4]=csub(E0,O0);
    x[1]=cadd(E1,o1); x[5]=csub(E1,o1);
    x[2]=cadd(E2,o2); x[6]=csub(E2,o2);
    x[3]=cadd(E3,o3); x[7]=csub(E3,o3);
}

// In-place 64x64 complex FFT, 512 threads, pitch 66. Unnormalized.
__device__ void fft2d(float2* A, const float2* stw, int tid, float S){
    int line = tid >> 3, n1 = tid & 7;
    #pragma unroll
    for (int dim = 0; dim < 2; dim++){
        int st   = dim ? 66 : 1;
        int base = dim ? line : line * 66;
        __syncthreads();
        float2 x[8];
        #pragma unroll
        for (int n2=0;n2<8;n2++) x[n2]=A[base+(n1+8*n2)*st];
        dft8(x,S);
        float2 y[8];
        #pragma unroll
        for (int k2=0;k2<8;k2++){
            float2 w = stw[n1*k2];
            if (S < 0.f) w.y = -w.y;
            y[k2]=cmul(x[k2],w);
        }
        __syncthreads();
        #pragma unroll
        for (int k2=0;k2<8;k2++) A[base+(8*k2+n1)*st]=y[k2];
        __syncthreads();
        #pragma unroll
        for (int q=0;q<8;q++) x[q]=A[base+(8*n1+q)*st];
        dft8(x,S);
        __syncthreads();
        #pragma unroll
        for (int k1=0;k1<8;k1++) A[base+(n1+8*k1)*st]=x[k1];
    }
    __syncthreads();
}

// ---------------- init: S=S0, N=eye, tw, Mhat(eye) & Nhat(eye) closed-form ----------------
__global__ void k_init(const float* __restrict__ S0) {
    int idx = blockIdx.x * 256 + threadIdx.x;       // grid 2048 -> idx < 524288
    if (idx < MDIM) g_Sb[0][idx] = S0[idx];
    if (idx < MK * KC) {
        int r = idx / KC, c = idx - r * KC;
        g_N[idx] = (c == r) ? 1.0f : 0.0f;
    }
    if (idx < 64) g_tw[idx] = twf(idx);
    if (idx < 128 * HW) {
        int plane = idx >> 12, pt = idx & 4095;
        int r = plane >> 1;
        int kh = pt >> 6, kw = pt & 63;
        // Mhat(eye): row r = delta at (c=0,h=0,w=r); gamma planes identical -> W^{r*kw}
        g_Mhat[idx] = twf((r * kw) & 63);
        // Nhat(eye): row r -> delta at (h=i, w=j) with r = j*36+i (k=0 only)
        int j = r / 36, i = r - j * 36;
        g_Nhat[idx] = cmul(twf((i * kh) & 63), twf((j * kw) & 63));
    }
}

// ---------------- role: gram0  g_Cm = alpha*I + 2*gamma * N N^T (spatial) ----------------
__device__ void gramN_role(float* buf, int a, const float* pa, const float* pg,
                           int NT, int tid) {
    for (int i = tid; i < KC; i += NT) buf[i] = g_N[a * KC + i];
    __syncthreads();
    int warp = tid >> 5, lane = tid & 31, nw = NT >> 5;
    for (int b = warp; b < MK; b += nw) {
        const float* xb = g_N + b * KC;
        float s = 0.f;
        for (int kk = lane; kk < KC; kk += 32) s += buf[kk] * xb[kk];
        #pragma unroll
        for (int o = 16; o; o >>= 1) s += __shfl_xor_sync(0xffffffffu, s, o);
        if (lane == 0) {
            float v = 2.0f * (*pg) * s;
            if (a == b) v += *pa;
            g_Cm[a * MK + b] = v;
        }
    }
}

// ---------------- role: gram1 in FREQUENCY domain (Parseval) ----------------
// Cn[a][b] = alpha*d(a,b) + (2*gamma/8192) * Re sum_g sum_pt Mhat_a conj(Mhat_b)
__device__ void gram1f_role(float2* sbuf, int a, const float* pa, const float* pg,
                            int NT, int tid) {
    int warp = tid >> 5, lane = tid & 31, nw = NT >> 5;   // nw=16 -> 4 b's per warp
    float accv[4] = {0.f, 0.f, 0.f, 0.f};
    for (int g2 = 0; g2 < 2; g2++) {
        __syncthreads();
        for (int i = tid; i < 4096; i += NT) sbuf[i] = g_Mhat[(a * 2 + g2) * HW + i];
        __syncthreads();
        int cnt = 0;
        for (int b2 = warp; b2 < MK; b2 += nw, cnt++) {
            const float2* xb = g_Mhat + (b2 * 2 + g2) * HW;
            float s = 0.f;
            for (int kk = lane; kk < 4096; kk += 32) {
                float2 u = sbuf[kk], v = xb[kk];
                s += u.x * v.x + u.y * v.y;
            }
            #pragma unroll
            for (int o = 16; o; o >>= 1) s += __shfl_xor_sync(0xffffffffu, s, o);
            accv[cnt] += s;
        }
    }
    int cnt = 0;
    for (int b2 = warp; b2 < MK; b2 += nw, cnt++) {
        if (lane == 0) {
            float v = 2.0f * (*pg) * accv[cnt] * (1.0f / 8192.0f);
            if (a == b2) v += *pa;
            g_Cm[a * MK + b2] = v;
        }
    }
}

// ---------------- role: 64x64 SPD inverse, in-place Gauss-Jordan ----------------
__device__ void inv_role(float* buf, int NT, int tid) {
    float* a    = buf;            // 64 x 65
    float* colk = buf + 4160;
    for (int idx = tid; idx < 64 * 64; idx += NT)
        a[(idx >> 6) * 65 + (idx & 63)] = g_Cm[idx];
    __syncthreads();
    for (int k = 0; k < 64; k++) {
        float p = 1.0f / a[k * 65 + k];
        for (int i = tid; i < 64; i += NT) colk[i] = a[i * 65 + k];
        __syncthreads();
        for (int j = tid; j < 64; j += NT)
            a[k * 65 + j] = (j == k) ? p : a[k * 65 + j] * p;
        __syncthreads();
        for (int idx = tid; idx < 64 * 64; idx += NT) {
            int i = idx >> 6, j = idx & 63;
            if (i != k)
                a[i * 65 + j] = (j == k) ? -colk[i] * p
                                         : a[i * 65 + j] - colk[i] * a[k * 65 + j];
        }
        __syncthreads();
    }
    for (int idx = tid; idx < 64 * 64; idx += NT)
        g_Inv[idx] = a[(idx >> 6) * 65 + (idx & 63)];
}

// ---------------- FFT mega-kernel (512 threads) ----------------
// mode 2: FWD N   (grid 128): padded N'(r) -> g_Nhat
// mode 3: IFFT A  (grid 2 (+64 gram0 riders)): sum(WhatP) -> g_Wr
// mode 5: OPC planes 0..63  (+64 gram1f riders): ifft(Mhat*conj(Lhat)) -> g_TB
// mode 6: OPC planes 64..127 (+1 inv1 rider)
__global__ __launch_bounds__(512) void k_fft(int mode, const float* __restrict__ pa,
                                             const float* __restrict__ pg) {
    __shared__ float2 sb[4288];          // A: 64x66 | stw: 64
    int tid = threadIdx.x, b = blockIdx.x;
    if (mode == 3 && b >= 2)  { gramN_role((float*)sb, b - 2, pa, pg, 512, tid); return; }
    if (mode == 5 && b >= 64) { gram1f_role(sb, b - 64, pa, pg, 512, tid); return; }
    if (mode == 6 && b >= 64) { inv_role((float*)sb, 512, tid); return; }

    float2* A   = sb;
    float2* stw = sb + 4224;
    if (tid < 64) stw[tid] = g_tw[tid];

    if (mode == 2) {
        int gamma = b & 1, r = b >> 1;
        float s = gamma ? -1.f : 1.f;
        const float* Nr = g_N + r * KC;
        for (int i = tid; i < 4096; i += 512) {
            int h = i >> 6, w = i & 63;
            float v = 0.f;
            if (h < 36 && w < 36) v = Nr[w * 36 + h] + s * Nr[(36 + w) * 36 + h];
            A[h * 66 + w] = make_float2(v, 0.f);
        }
        fft2d(A, stw, tid, 1.f);
        float2* d = g_Nhat + b * HW;
        for (int i = tid; i < 4096; i += 512) d[i] = A[(i >> 6) * 66 + (i & 63)];
    } else if (mode == 3) {
        int gamma = b;
        for (int i = tid; i < 4096; i += 512) {
            float2 acc = make_float2(0.f, 0.f);
            #pragma unroll
            for (int sgrp = 0; sgrp < 8; sgrp++)
                acc = cadd(acc, g_WhatP[sgrp * 2 * HW + gamma * HW + i]);
            A[(i >> 6) * 66 + (i & 63)] = acc;
        }
        fft2d(A, stw, tid, -1.f);
        for (int i = tid; i < 4096; i += 512)
            g_Wr[gamma * HW + i] = A[(i >> 6) * 66 + (i & 63)].x;
    } else {
        int p = (mode == 6) ? 64 + b : b;     // plane index (r*2+gamma)
        const float2* Mh = g_Mhat + p * HW;
        const float2* Lh = g_Lhat + (p & 1) * HW;
        for (int i = tid; i < 4096; i += 512)
            A[(i >> 6) * 66 + (i & 63)] = cmulc(Mh[i], Lh[i]);
        fft2d(A, stw, tid, -1.f);
        for (int i = tid; i < 4096; i += 512)
            g_TB[p * HW + i] = A[(i >> 6) * 66 + (i & 63)].x;
    }
}

// ---------------- opA partial sums: WhatP[rg] = sum_{r in rg} Mhat_r * conj(Nhat_r) -------
__global__ __launch_bounds__(256) void k_opAsum() {
    int b = blockIdx.x;                       // 256 blocks
    int rg = b & 7, chunk = b >> 3;
    int gw = chunk * 256 + threadIdx.x;       // 0..8191
    int gamma = gw >> 12, pt = gw & 4095;
    float2 acc = make_float2(0.f, 0.f);
    #pragma unroll
    for (int rr = 0; rr < 8; rr++) {
        int r = rg * 8 + rr;
        float2 a  = g_Mhat[(r * 2 + gamma) * HW + pt];
        float2 bb = g_Nhat[(r * 2 + gamma) * HW + pt];
        acc.x += a.x * bb.x + a.y * bb.y;
        acc.y += a.y * bb.x - a.x * bb.y;
    }
    g_WhatP[rg * 2 * HW + gw] = acc;
}

// ---------------- k_lelem: elem update + forward L-FFT (per gamma) + inv0 rider -----------
// grid 3 (b=0,1 fft gammas; b=2 inv0) or grid 1 when final.
__global__ __launch_bounds__(512) void k_lelem(const float* __restrict__ img,
                                               const float* __restrict__ pg,
                                               const float* __restrict__ pb,
                                               int par, int final, float* __restrict__ out) {
    __shared__ float2 sb[4288];
    int tid = threadIdx.x, b = blockIdx.x;
    if (b == 2) { inv_role((float*)sb, 512, tid); return; }
    float2* A   = sb;
    float2* stw = sb + 4224;
    if (tid < 64) stw[tid] = g_tw[tid];
    float gam = *pg, bet = *pb;
    const float* Sc = g_Sb[par];
    float*       Sn = g_Sb[par ^ 1];
    float sg = b ? -1.f : 1.f;

    for (int i = tid; i < 4096; i += 512) {
        float w0 = g_Wr[i], w1 = g_Wr[HW + i];
        float ak0 = (w0 + w1) * AKSCL;
        float ak1 = (w0 - w1) * AKSCL;
        float i0 = img[i], i1 = img[HW + i];
        float l0 = fminf(fmaxf((i0 - Sc[i]      + gam * ak0) / (gam + 1.f), 0.f), 1.f);
        float l1 = fminf(fmaxf((i1 - Sc[HW + i] + gam * ak1) / (gam + 1.f), 0.f), 1.f);
        if (b == 0) {
            Sn[i]      = (i0 - l0) / (bet + 1.f);
            Sn[HW + i] = (i1 - l1) / (bet + 1.f);
            if (final) { out[i] = l0; out[HW + i] = l1; }
        }
        A[(i >> 6) * 66 + (i & 63)] = make_float2(l0 + sg * l1, 0.f);
    }
    if (final) return;
    fft2d(A, stw, tid, 1.f);
    float2* d = g_Lhat + b * HW;
    for (int i = tid; i < 4096; i += 512) d[i] = A[(i >> 6) * 66 + (i & 63)];
}

// ---------------- k_mhat: Mhat = 2*gamma * Inv @ (Nhat .* Lhat), all in freq --------------
// (FFT(IFFT_unnorm(X)/4096) = X: the 4096s cancel, so scale is exactly 2*gamma.)
// grid 128: gamma = b>>6, 64-point chunk = b&63. 256 threads.
__global__ __launch_bounds__(256) void k_mhat(const float* __restrict__ pg) {
    __shared__ float  As[4096];          // Inv
    __shared__ float2 Xs[4096];          // [q][ptloc] = Nhat_q * Lhat
    int tid = threadIdx.x, b = blockIdx.x;
    int gamma = b >> 6, chunk = b & 63;
    int pt0 = chunk * 64;
    for (int i = tid; i < 4096; i += 256) As[i] = g_Inv[i];
    const float2* Lh = g_Lhat + gamma * HW + pt0;
    for (int i = tid; i < 4096; i += 256) {
        int q = i >> 6, pl = i & 63;
        Xs[i] = cmul(g_Nhat[(q * 2 + gamma) * HW + pt0 + pl], Lh[pl]);
    }
    __syncthreads();
    int tx = tid & 63, ty = tid >> 6;
    float ar[16], ai[16];
    #pragma unroll
    for (int u = 0; u < 16; u++) { ar[u] = 0.f; ai[u] = 0.f; }
    for (int q = 0; q < 64; q++) {
        float2 xv = Xs[q * 64 + tx];
        #pragma unroll
        for (int u = 0; u < 16; u++) {
            float w = As[(ty * 16 + u) * 64 + q];
            ar[u] += w * xv.x;
            ai[u] += w * xv.y;
        }
    }
    float sc = 2.0f * (*pg);
    #pragma unroll
    for (int u = 0; u < 16; u++) {
        int uu = ty * 16 + u;
        g_Mhat[(uu * 2 + gamma) * HW + pt0 + tx] = make_float2(sc * ar[u], sc * ai[u]);
    }
}

// ---------------- smallmm: N = 2*gamma * Inv2 @ T  (T gathered from TB corner) ------------
__global__ void __launch_bounds__(256) k_smallmm(const float* __restrict__ pg) {
    __shared__ float As[4096];
    __shared__ float Xs[4096];
    int tid = threadIdx.x;
    int tx = tid & 63, ty = tid >> 6;
    int cb = blockIdx.x * 64;
    const float SCL = 1.0f / 8192.0f;
    for (int i = tid; i < 4096; i += 256) As[i] = g_Inv[i];
    for (int i = tid; i < 4096; i += 256) {
        int q = i >> 6, cc = cb + (i & 63);
        float v = 0.f;
        if (cc < KC) {
            int k2 = cc / 1296; int rem = cc - k2 * 1296;
            int j  = rem / 36;  int ii = rem - j * 36;
            int p2 = ii * 64 + j;
            float sgk = k2 ? -1.f : 1.f;
            v = (g_TB[(q * 2) * HW + p2] + sgk * g_TB[(q * 2 + 1) * HW + p2]) * SCL;
        }
        Xs[i] = v;
    }
    __syncthreads();
    float acc[16];
    #pragma unroll
    for (int u = 0; u < 16; u++) acc[u] = 0.f;
    for (int q = 0; q < 64; q++) {
        float xv = Xs[q * 64 + tx];
        #pragma unroll
        for (int u = 0; u < 16; u++)
            acc[u] += As[(ty * 16 + u) * 64 + q] * xv;
    }
    int col = cb + tx;
    if (col < KC) {
        float sc = 2.0f * (*pg);
        #pragma unroll
        for (int u = 0; u < 16; u++)
            g_N[(ty * 16 + u) * KC + col] = sc * acc[u];
    }
}

// =====================================================================================
extern "C" void kernel_launch(void* const* d_in, const int* in_sizes, int n_in,
                              void* d_out, int out_size) {
    const float* img = (const float*)d_in[0];
    const float* S0  = (const float*)d_in[1];
    const float* pa  = (const float*)d_in[2];   // alpha
    const float* pb  = (const float*)d_in[3];   // beta
    const float* pg  = (const float*)d_in[4];   // gamma
    float* out = (float*)d_out;
    (void)in_sizes; (void)n_in; (void)out_size;

    k_init<<<2048, 256>>>(S0);                   // S, N, tw, Mhat(eye), Nhat(eye)

    for (int it = 0; it < NSTEPS; it++) {
        int last = (it == NSTEPS - 1);
        k_opAsum<<<256, 256>>>();                               // WhatP = Mhat conj(Nhat) partials
        k_fft<<<last ? 2 : 66, 512>>>(3, pa, pg);               // Wr = ifft(sum) (+gram0)
        k_lelem<<<last ? 1 : 3, 512>>>(img, pg, pb, it & 1, last, out);  // elem + Lhat (+inv0)
        if (!last) {
            k_mhat<<<128, 256>>>(pg);                           // Mhat = 2g Inv@(Nhat.Lhat)
            k_fft<<<128, 512>>>(5, pa, pg);                     // TB planes 0..63 (+gram1 freq)
            k_fft<<<65, 512>>>(6, pa, pg);                      // TB planes 64..127 (+inv1)
            k_smallmm<<<(KC + 63) / 64, 256>>>(pg);             // N = 2g Inv2 @ T
            k_fft<<<128, 512>>>(2, pa, pg);                     // Nhat
        }
    }
}